// round 7
// baseline (speedup 1.0000x reference)
#include <cuda_runtime.h>
#include <cuda_fp16.h>
#include <cuda_bf16.h>
#include <cstdint>
#include <cstddef>

#define Bc    2
#define Tc    2048
#define Dc    2048
#define Hc    16
#define KEYD  2048
#define VALD  2048
#define CONVD 6144
#define BT    4096   // B*T

typedef unsigned short u16;
typedef uint32_t u32;

// ---------------- scratch (device globals: allocation-free) ----------------
__device__ float g_mixed[(size_t)BT * CONVD];   // qkv pre-conv (fp32)
__device__ float g_qkv[(size_t)BT * CONVD];     // post conv+silu (+l2norm in place)
__device__ float g_gb[2 * BT * Hc];             // g then beta
__device__ float g_z[(size_t)BT * VALD];
__device__ float g_od[(size_t)BT * VALD];       // delta-rule output
__device__ float g_Cab[(size_t)BT * 32];        // a/b projection pre-activation

// fp16 operands: A side split hi/lo (exact), B side single fp16
__device__ u16 g_hsA_hi[(size_t)BT * Dc];
__device__ u16 g_hsA_lo[(size_t)BT * Dc];
__device__ u16 g_Wq[(size_t)CONVD * Dc];
__device__ u16 g_Wz[(size_t)VALD * Dc];
__device__ u16 g_Wo[(size_t)Dc * VALD];
__device__ u16 g_ab[(size_t)32 * Dc];
__device__ u16 g_y_hi[(size_t)BT * VALD];
__device__ u16 g_y_lo[(size_t)BT * VALD];

// ---------------- helpers ----------------
__device__ __forceinline__ u16 h16bits(float x) {
    __half h = __float2half_rn(x);
    return *reinterpret_cast<u16*>(&h);
}
__device__ __forceinline__ float h16val(u16 u) {
    __half h;
    *reinterpret_cast<u16*>(&h) = u;
    return __half2float(h);
}
__device__ __forceinline__ u32 smem_u32(const void* p) {
    u32 a;
    asm("{ .reg .u64 t; cvta.to.shared.u64 t, %1; cvt.u32.u64 %0, t; }" : "=r"(a) : "l"(p));
    return a;
}
#define SWZ(x) ((x) ^ (((x) >> 3) & 0x70))

__device__ __forceinline__ void cp16(u32 s, const void* g) {
    asm volatile("cp.async.cg.shared.global [%0], [%1], 16;" :: "r"(s), "l"(g));
}
__device__ __forceinline__ void ldsm4(u32* r, u32 a) {
    asm volatile("ldmatrix.sync.aligned.m8n8.x4.shared.b16 {%0,%1,%2,%3}, [%4];"
                 : "=r"(r[0]), "=r"(r[1]), "=r"(r[2]), "=r"(r[3]) : "r"(a));
}
__device__ __forceinline__ void mma16816(float* c, const u32* a, const u32* b) {
    asm volatile(
        "mma.sync.aligned.m16n8k16.row.col.f32.f16.f16.f32 "
        "{%0,%1,%2,%3}, {%4,%5,%6,%7}, {%8,%9}, {%0,%1,%2,%3};"
        : "+f"(c[0]), "+f"(c[1]), "+f"(c[2]), "+f"(c[3])
        : "r"(a[0]), "r"(a[1]), "r"(a[2]), "r"(a[3]), "r"(b[0]), "r"(b[1]));
}

// ---------------- operand conversion kernels ----------------
__global__ void cvt_hilo_kernel(const float4* __restrict__ in,
                                ushort4* __restrict__ hi, ushort4* __restrict__ lo,
                                int n4) {
    int i = blockIdx.x * 256 + threadIdx.x;
    if (i >= n4) return;
    float4 v = in[i];
    ushort4 H, L;
    H.x = h16bits(v.x); L.x = h16bits(v.x - h16val(H.x));
    H.y = h16bits(v.y); L.y = h16bits(v.y - h16val(H.y));
    H.z = h16bits(v.z); L.z = h16bits(v.z - h16val(H.z));
    H.w = h16bits(v.w); L.w = h16bits(v.w - h16val(H.w));
    hi[i] = H; lo[i] = L;
}

// transpose + fp16 convert: W [Kd, N] fp32 -> T [N, Kd] fp16
__global__ void transpose_cvt_kernel(const float* __restrict__ W,
                                     u16* __restrict__ Th, int Kd, int N) {
    __shared__ float t[32][33];
    int n0 = blockIdx.x * 32, k0 = blockIdx.y * 32;
    int x = threadIdx.x, y = threadIdx.y;   // 32 x 8
#pragma unroll
    for (int i = 0; i < 4; ++i)
        t[y + 8 * i][x] = W[(size_t)(k0 + y + 8 * i) * N + n0 + x];
    __syncthreads();
#pragma unroll
    for (int i = 0; i < 4; ++i) {
        float v = t[x][y + 8 * i];
        Th[(size_t)(n0 + y + 8 * i) * Kd + k0 + x] = h16bits(v);
    }
}

// Wa,Wb [D,16] -> [32, D] fp16 (rows 0-15 = Wa^T, 16-31 = Wb^T)
__global__ void transpose_ab_kernel(const float* __restrict__ Wa,
                                    const float* __restrict__ Wb,
                                    u16* __restrict__ T) {
    int n = blockIdx.y;
    int k = blockIdx.x * 256 + threadIdx.x;
    const float* W = (n < 16) ? Wa : Wb;
    T[(size_t)n * Dc + k] = h16bits(W[(size_t)k * Hc + (n & 15)]);
}

// ---------------- HMMA GEMM: C[M,N] = A[M,K] @ Bt[N,K]^T ----------------
// A fp16 hi/lo (2 products, exact A), B single fp16; fp32 accumulate.
// 256 threads = 8 warps (4m x 2n). BK=64. 4-stage cp.async pipeline, 1 sync/iter.
// Inner loop: hi pass over all 16 accumulators, then lo pass (RAW distance 16).
template <int BN>
__global__ __launch_bounds__(256, 1)
void mma_gemm(const u16* __restrict__ Ahi, const u16* __restrict__ Alo,
              const u16* __restrict__ Bh, float* __restrict__ C,
              int M, int N, int Kd) {
    extern __shared__ __align__(1024) char smem[];
    constexpr int ATILE = 128 * 128;          // bytes per A half-tile
    constexpr int BTILE = BN * 128;
    constexpr int STAGE = 2 * ATILE + BTILE;
    constexpr int WN = BN / 2;                // warp n-tile
    constexpr int NG = WN / 16;               // ldmatrix.x4 groups per k16
    const int tid = threadIdx.x, lane = tid & 31, wid = tid >> 5;
    const int wm = (wid & 3) * 32;
    const int wn = (wid >> 2) * WN;
    const int m0 = blockIdx.y * 128, n0 = blockIdx.x * BN;
    const int ktiles = Kd >> 6;
    const u32 sb = smem_u32(smem);

    const u16* srcs[3] = {Ahi + (size_t)m0 * Kd, Alo + (size_t)m0 * Kd,
                          Bh + (size_t)n0 * Kd};
    const int rows[3] = {128, 128, BN};
    const u32 offs[3] = {0, ATILE, 2 * ATILE};

    auto issue = [&](int kt) {
        const int ko = kt << 6;
        const u32 st = sb + (u32)(kt & 3) * STAGE;
#pragma unroll
        for (int r = 0; r < 3; ++r) {
            for (int c = tid; c < rows[r] * 8; c += 256) {
                int rr = c >> 3, u = c & 7;
                cp16(st + offs[r] + SWZ(rr * 128 + u * 16),
                     srcs[r] + (size_t)rr * Kd + ko + u * 8);
            }
        }
    };

    float acc[2][WN / 8][4];
#pragma unroll
    for (int i = 0; i < 2; ++i)
#pragma unroll
        for (int j = 0; j < WN / 8; ++j)
#pragma unroll
            for (int l = 0; l < 4; ++l) acc[i][j][l] = 0.f;

    // prologue: stages 0..2
    issue(0);
    asm volatile("cp.async.commit_group;");
    issue(1);
    asm volatile("cp.async.commit_group;");
    issue(2);
    asm volatile("cp.async.commit_group;");

    for (int kt = 0; kt < ktiles; ++kt) {
        asm volatile("cp.async.wait_group 2;" ::: "memory");
        __syncthreads();
        if (kt + 3 < ktiles) issue(kt + 3);
        asm volatile("cp.async.commit_group;");

        const u32 Ab = sb + (u32)(kt & 3) * STAGE;
        const u32 Bb = Ab + 2 * ATILE;
#pragma unroll
        for (int ks = 0; ks < 4; ++ks) {
            u32 ah[2][4], al[2][4], bh[NG][4];
            const int arow = wm + (lane & 15);
            const int acol = ks * 32 + ((lane >> 4) << 4);
#pragma unroll
            for (int mf = 0; mf < 2; ++mf) {
                u32 ad = Ab + SWZ((arow + mf * 16) * 128 + acol);
                ldsm4(ah[mf], ad);
                ldsm4(al[mf], ad + ATILE);
            }
            const int brow = wn + (lane & 7) + ((lane >> 4) << 3);
            const int bcol = ks * 32 + ((lane & 8) << 1);
#pragma unroll
            for (int g = 0; g < NG; ++g)
                ldsm4(bh[g], Bb + SWZ((brow + g * 16) * 128 + bcol));
            // hi pass: all accumulators once (independent mmas)
#pragma unroll
            for (int mf = 0; mf < 2; ++mf)
#pragma unroll
                for (int g = 0; g < NG; ++g) {
                    mma16816(acc[mf][2 * g + 0], ah[mf], &bh[g][0]);
                    mma16816(acc[mf][2 * g + 1], ah[mf], &bh[g][2]);
                }
            // lo pass: same accumulators, RAW distance = 2*NG*2 instructions
#pragma unroll
            for (int mf = 0; mf < 2; ++mf)
#pragma unroll
                for (int g = 0; g < NG; ++g) {
                    mma16816(acc[mf][2 * g + 0], al[mf], &bh[g][0]);
                    mma16816(acc[mf][2 * g + 1], al[mf], &bh[g][2]);
                }
        }
    }

    // epilogue: direct gmem stores
#pragma unroll
    for (int mf = 0; mf < 2; ++mf)
#pragma unroll
        for (int f = 0; f < WN / 8; ++f) {
            int row = m0 + wm + mf * 16 + (lane >> 2);
            int col = n0 + wn + f * 8 + (lane & 3) * 2;
            float2 lo2, hi2;
            lo2.x = acc[mf][f][0]; lo2.y = acc[mf][f][1];
            hi2.x = acc[mf][f][2]; hi2.y = acc[mf][f][3];
            *(float2*)&C[(size_t)row * N + col] = lo2;
            *(float2*)&C[(size_t)(row + 8) * N + col] = hi2;
        }
}

// ---------------- depthwise causal conv (K=4) + silu ----------------
__global__ void conv_silu_kernel(const float* __restrict__ mixed,
                                 const float* __restrict__ cw,
                                 float* __restrict__ out) {
    const int c  = blockIdx.x * 128 + threadIdx.x;
    const int b  = blockIdx.z;
    const int t0 = blockIdx.y * 256;
    const float w0 = cw[c * 4 + 0], w1 = cw[c * 4 + 1];
    const float w2 = cw[c * 4 + 2], w3 = cw[c * 4 + 3];
    const float* base  = mixed + (size_t)b * Tc * CONVD + c;
    float*       obase = out   + (size_t)b * Tc * CONVD + c;
    float xm3 = (t0 >= 3) ? base[(size_t)(t0 - 3) * CONVD] : 0.f;
    float xm2 = (t0 >= 2) ? base[(size_t)(t0 - 2) * CONVD] : 0.f;
    float xm1 = (t0 >= 1) ? base[(size_t)(t0 - 1) * CONVD] : 0.f;
#pragma unroll 4
    for (int t = t0; t < t0 + 256; ++t) {
        float x = base[(size_t)t * CONVD];
        float y = w0 * xm3 + w1 * xm2 + w2 * xm1 + w3 * x;
        float s = 1.f / (1.f + expf(-y));
        obase[(size_t)t * CONVD] = y * s;
        xm3 = xm2; xm2 = xm1; xm1 = x;
    }
}

// ---------------- per-head L2 norm for q and k (in place) ----------------
__global__ void l2norm_kernel(float* __restrict__ qkv) {
    const int warp = threadIdx.x >> 5, lane = threadIdx.x & 31;
    const int vec = blockIdx.x * 8 + warp;      // [0, 2*BT*H)
    const int qk = vec >> 16;                   // BT*H == 65536
    const int r  = vec & 65535;
    const int bt = r >> 4, h = r & 15;
    float* p = qkv + (size_t)bt * CONVD + qk * KEYD + h * 128 + lane * 4;
    float4 v = *(float4*)p;
    float ss = v.x * v.x + v.y * v.y + v.z * v.z + v.w * v.w;
#pragma unroll
    for (int off = 16; off; off >>= 1) ss += __shfl_xor_sync(~0u, ss, off);
    float scale = rsqrtf(ss + 1e-6f);
    if (qk == 0) scale *= 0.08838834764831845f;   // DK^-0.5
    v.x *= scale; v.y *= scale; v.z *= scale; v.w *= scale;
    *(float4*)p = v;
}

// ---------------- a/b activation ----------------
__global__ void ab_act_kernel(const float* __restrict__ Cab,
                              const float* __restrict__ dt_bias,
                              const float* __restrict__ A_log,
                              float* __restrict__ gb) {
    int i = blockIdx.x * 256 + threadIdx.x;     // over BT*16
    int m = i >> 4, h = i & 15;
    float av = Cab[(size_t)m * 32 + h];
    float bv = Cab[(size_t)m * 32 + 16 + h];
    float x = av + dt_bias[h];
    float sp = (x > 20.f) ? x : log1pf(expf(x));
    gb[i] = -expf(A_log[h]) * sp;
    gb[(size_t)BT * Hc + i] = 1.f / (1.f + expf(-bv));
}

// ---------------- gated delta rule scan (single merged reduction tree) ----------
__global__ __launch_bounds__(256, 1)
void scan_kernel(const float* __restrict__ qkv, const float* __restrict__ gb,
                 float* __restrict__ od) {
    const int blk  = blockIdx.x;
    const int vblk = blk & 3;
    const int h    = (blk >> 2) & 15;
    const int b    = blk >> 6;
    const int tid = threadIdx.x;
    const int tk = tid & 15, tv = tid >> 4;
    const int vbase = vblk * 32 + tv * 2;

    const float* qp = qkv + (size_t)b * Tc * CONVD + h * 128 + tk * 8;
    const float* kp = qp + KEYD;
    const float* vp = qkv + (size_t)b * Tc * CONVD + 2 * KEYD + h * 128 + vbase;
    const float* gp = gb + (size_t)b * Tc * Hc + h;
    const float* bp = gp + (size_t)BT * Hc;
    float* op = od + ((size_t)b * Tc * Hc + h) * 128 + vbase;

    float S[8][2];
#pragma unroll
    for (int i = 0; i < 8; ++i) { S[i][0] = 0.f; S[i][1] = 0.f; }

    for (int t = 0; t < Tc; ++t) {
        float4 q0 = *(const float4*)qp, q1 = *(const float4*)(qp + 4);
        float4 k0 = *(const float4*)kp, k1 = *(const float4*)(kp + 4);
        float2 vv = *(const float2*)vp;
        float gg = *gp, bb = *bp;
        float eg = __expf(gg);
        float kr[8] = {k0.x, k0.y, k0.z, k0.w, k1.x, k1.y, k1.z, k1.w};
        float qr[8] = {q0.x, q0.y, q0.z, q0.w, q1.x, q1.y, q1.z, q1.w};

        // all dot products against S_old + q.k, one reduction tree
        float ks0 = 0.f, ks1 = 0.f, qs0 = 0.f, qs1 = 0.f, qk = 0.f;
#pragma unroll
        for (int i = 0; i < 8; ++i) {
            ks0 = fmaf(kr[i], S[i][0], ks0);
            ks1 = fmaf(kr[i], S[i][1], ks1);
            qs0 = fmaf(qr[i], S[i][0], qs0);
            qs1 = fmaf(qr[i], S[i][1], qs1);
            qk  = fmaf(qr[i], kr[i], qk);
        }
#pragma unroll
        for (int off = 8; off; off >>= 1) {
            ks0 += __shfl_xor_sync(~0u, ks0, off);
            ks1 += __shfl_xor_sync(~0u, ks1, off);
            qs0 += __shfl_xor_sync(~0u, qs0, off);
            qs1 += __shfl_xor_sync(~0u, qs1, off);
            qk  += __shfl_xor_sync(~0u, qk, off);
        }
        float d0 = (vv.x - eg * ks0) * bb;
        float d1 = (vv.y - eg * ks1) * bb;
        if (tk == 0) {
            float2 ov;
            ov.x = fmaf(qk, d0, eg * qs0);
            ov.y = fmaf(qk, d1, eg * qs1);
            *(float2*)op = ov;
        }
#pragma unroll
        for (int i = 0; i < 8; ++i) {
            S[i][0] = fmaf(kr[i], d0, eg * S[i][0]);
            S[i][1] = fmaf(kr[i], d1, eg * S[i][1]);
        }
        qp += CONVD; kp += CONVD; vp += CONVD;
        gp += Hc; bp += Hc;
        op += (size_t)Hc * 128;
    }
}

// ---------------- gated RMSNorm -> fp16 hi/lo ----------------
__global__ void gate_norm_kernel(const float* __restrict__ od,
                                 const float* __restrict__ z,
                                 const float* __restrict__ nw,
                                 ushort4* __restrict__ yhi,
                                 ushort4* __restrict__ ylo) {
    const int warp = threadIdx.x >> 5, lane = threadIdx.x & 31;
    const int vec = blockIdx.x * 8 + warp;      // bt*H + h
    const float* opv = od + (size_t)vec * 128 + lane * 4;
    const float* zpv = z  + (size_t)vec * 128 + lane * 4;
    float4 o  = *(const float4*)opv;
    float4 zz = *(const float4*)zpv;
    float4 og;
    og.x = o.x * (zz.x / (1.f + expf(-zz.x)));
    og.y = o.y * (zz.y / (1.f + expf(-zz.y)));
    og.z = o.z * (zz.z / (1.f + expf(-zz.z)));
    og.w = o.w * (zz.w / (1.f + expf(-zz.w)));
    float ss = og.x * og.x + og.y * og.y + og.z * og.z + og.w * og.w;
#pragma unroll
    for (int off = 16; off; off >>= 1) ss += __shfl_xor_sync(~0u, ss, off);
    float r = rsqrtf(ss * (1.f / 128.f) + 1e-6f);
    float4 w = *(const float4*)&nw[lane * 4];
    float4 out;
    out.x = og.x * r * w.x; out.y = og.y * r * w.y;
    out.z = og.z * r * w.z; out.w = og.w * r * w.w;
    ushort4 H, L;
    H.x = h16bits(out.x); L.x = h16bits(out.x - h16val(H.x));
    H.y = h16bits(out.y); L.y = h16bits(out.y - h16val(H.y));
    H.z = h16bits(out.z); L.z = h16bits(out.z - h16val(H.z));
    H.w = h16bits(out.w); L.w = h16bits(out.w - h16val(H.w));
    yhi[(size_t)vec * 32 + lane] = H;
    ylo[(size_t)vec * 32 + lane] = L;
}

// ---------------- launch ----------------
extern "C" void kernel_launch(void* const* d_in, const int* in_sizes, int n_in,
                              void* d_out, int out_size) {
    const float* hs      = (const float*)d_in[0];
    const float* W_qkv   = (const float*)d_in[1];
    const float* conv_w  = (const float*)d_in[2];
    const float* W_z     = (const float*)d_in[3];
    const float* W_b     = (const float*)d_in[4];
    const float* W_a     = (const float*)d_in[5];
    const float* dt_bias = (const float*)d_in[6];
    const float* A_log   = (const float*)d_in[7];
    const float* norm_w  = (const float*)d_in[8];
    const float* W_out   = (const float*)d_in[9];
    float* out = (float*)d_out;

    float *mixed, *qkv, *gb, *z, *od, *Cab;
    u16 *hsA_hi, *hsA_lo, *Wq, *Wz, *Wo, *ab, *y_hi, *y_lo;
    cudaGetSymbolAddress((void**)&mixed, g_mixed);
    cudaGetSymbolAddress((void**)&qkv,   g_qkv);
    cudaGetSymbolAddress((void**)&gb,    g_gb);
    cudaGetSymbolAddress((void**)&z,     g_z);
    cudaGetSymbolAddress((void**)&od,    g_od);
    cudaGetSymbolAddress((void**)&Cab,   g_Cab);
    cudaGetSymbolAddress((void**)&hsA_hi, g_hsA_hi);
    cudaGetSymbolAddress((void**)&hsA_lo, g_hsA_lo);
    cudaGetSymbolAddress((void**)&Wq,  g_Wq);
    cudaGetSymbolAddress((void**)&Wz,  g_Wz);
    cudaGetSymbolAddress((void**)&Wo,  g_Wo);
    cudaGetSymbolAddress((void**)&ab,  g_ab);
    cudaGetSymbolAddress((void**)&y_hi, g_y_hi);
    cudaGetSymbolAddress((void**)&y_lo, g_y_lo);

    const int smem128 = 4 * (2 * 16384 + 128 * 128);   // 196608
    const int smem32  = 4 * (2 * 16384 + 32 * 128);    // 147456
    cudaFuncSetAttribute(mma_gemm<128>, cudaFuncAttributeMaxDynamicSharedMemorySize, smem128);
    cudaFuncSetAttribute(mma_gemm<32>,  cudaFuncAttributeMaxDynamicSharedMemorySize, smem32);

    // operand prep
    cvt_hilo_kernel<<<(BT * Dc / 4 + 255) / 256, 256>>>(
        (const float4*)hs, (ushort4*)hsA_hi, (ushort4*)hsA_lo, BT * Dc / 4);
    transpose_cvt_kernel<<<dim3(CONVD / 32, Dc / 32), dim3(32, 8)>>>(W_qkv, Wq, Dc, CONVD);
    transpose_cvt_kernel<<<dim3(VALD / 32, Dc / 32), dim3(32, 8)>>>(W_z, Wz, Dc, VALD);
    transpose_cvt_kernel<<<dim3(Dc / 32, VALD / 32), dim3(32, 8)>>>(W_out, Wo, VALD, Dc);
    transpose_ab_kernel<<<dim3(Dc / 256, 32), 256>>>(W_a, W_b, ab);

    // 1. mixed = hs @ W_qkv
    mma_gemm<128><<<dim3(CONVD / 128, BT / 128), 256, smem128>>>(
        hsA_hi, hsA_lo, Wq, mixed, BT, CONVD, Dc);
    // 2. depthwise causal conv + silu
    conv_silu_kernel<<<dim3(CONVD / 128, Tc / 256, Bc), 128>>>(mixed, conv_w, qkv);
    // 3. l2norm q, k
    l2norm_kernel<<<(2 * BT * Hc) / 8, 256>>>(qkv);
    // 4. a/b projection (N=32 GEMM) + activations
    mma_gemm<32><<<dim3(1, BT / 128), 256, smem32>>>(
        hsA_hi, hsA_lo, ab, Cab, BT, 32, Dc);
    ab_act_kernel<<<(BT * Hc) / 256, 256>>>(Cab, dt_bias, A_log, gb);
    // 5. z = hs @ W_z
    mma_gemm<128><<<dim3(VALD / 128, BT / 128), 256, smem128>>>(
        hsA_hi, hsA_lo, Wz, z, BT, VALD, Dc);
    // 6. gated delta rule scan
    scan_kernel<<<Bc * Hc * 4, 256>>>(qkv, gb, od);
    // 7. gated RMSNorm -> y hi/lo
    gate_norm_kernel<<<(BT * Hc) / 8, 256>>>(od, z, norm_w, (ushort4*)y_hi, (ushort4*)y_lo);
    // 8. out = y @ W_out
    mma_gemm<128><<<dim3(Dc / 128, BT / 128), 256, smem128>>>(
        y_hi, y_lo, Wo, out, BT, Dc, Dc);
}

// round 8
// speedup vs baseline: 1.2049x; 1.2049x over previous
#include <cuda_runtime.h>
#include <cuda_fp16.h>
#include <cstdint>
#include <cstddef>

#define Bc    2
#define Tc    2048
#define Dc    2048
#define Hc    16
#define KEYD  2048
#define VALD  2048
#define CONVD 6144
#define BT    4096   // B*T

typedef unsigned short u16;
typedef uint32_t u32;

// ---------------- scratch (device globals: allocation-free) ----------------
__device__ float g_mixed[(size_t)BT * CONVD];   // qkv pre-conv (fp32)
__device__ float g_qkv[(size_t)BT * CONVD];     // post conv+silu (+l2norm in place)
__device__ float g_gb[2 * BT * Hc];             // g then beta
__device__ float g_z[(size_t)BT * VALD];
__device__ float g_od[(size_t)BT * VALD];       // delta-rule output
__device__ float g_Cab[(size_t)BT * 32];        // a/b projection pre-activation

// fp16 operands
__device__ u16 g_hsA[(size_t)BT * Dc];
__device__ u16 g_Wq[(size_t)CONVD * Dc];
__device__ u16 g_Wz[(size_t)VALD * Dc];
__device__ u16 g_Wo[(size_t)Dc * VALD];
__device__ u16 g_ab[(size_t)32 * Dc];
__device__ u16 g_y[(size_t)BT * VALD];

// ---------------- helpers ----------------
__device__ __forceinline__ u16 h16bits(float x) {
    __half h = __float2half_rn(x);
    return *reinterpret_cast<u16*>(&h);
}
__device__ __forceinline__ u32 smem_u32(const void* p) {
    u32 a;
    asm("{ .reg .u64 t; cvta.to.shared.u64 t, %1; cvt.u32.u64 %0, t; }" : "=r"(a) : "l"(p));
    return a;
}
#define SWZ(x) ((x) ^ (((x) >> 3) & 0x70))

__device__ __forceinline__ void cp16(u32 s, const void* g) {
    asm volatile("cp.async.cg.shared.global [%0], [%1], 16;" :: "r"(s), "l"(g));
}
__device__ __forceinline__ void ldsm4(u32* r, u32 a) {
    asm volatile("ldmatrix.sync.aligned.m8n8.x4.shared.b16 {%0,%1,%2,%3}, [%4];"
                 : "=r"(r[0]), "=r"(r[1]), "=r"(r[2]), "=r"(r[3]) : "r"(a));
}
__device__ __forceinline__ void mma16816(float* c, const u32* a, const u32* b) {
    asm volatile(
        "mma.sync.aligned.m16n8k16.row.col.f32.f16.f16.f32 "
        "{%0,%1,%2,%3}, {%4,%5,%6,%7}, {%8,%9}, {%0,%1,%2,%3};"
        : "+f"(c[0]), "+f"(c[1]), "+f"(c[2]), "+f"(c[3])
        : "r"(a[0]), "r"(a[1]), "r"(a[2]), "r"(a[3]), "r"(b[0]), "r"(b[1]));
}

// ---------------- operand conversion kernels ----------------
__global__ void cvt_h16_kernel(const float4* __restrict__ in,
                               ushort4* __restrict__ out, int n4) {
    int i = blockIdx.x * 256 + threadIdx.x;
    if (i >= n4) return;
    float4 v = in[i];
    ushort4 H;
    H.x = h16bits(v.x); H.y = h16bits(v.y);
    H.z = h16bits(v.z); H.w = h16bits(v.w);
    out[i] = H;
}

// transpose + fp16 convert: W [Kd, N] fp32 -> T [N, Kd] fp16
__global__ void transpose_cvt_kernel(const float* __restrict__ W,
                                     u16* __restrict__ Th, int Kd, int N) {
    __shared__ float t[32][33];
    int n0 = blockIdx.x * 32, k0 = blockIdx.y * 32;
    int x = threadIdx.x, y = threadIdx.y;   // 32 x 8
#pragma unroll
    for (int i = 0; i < 4; ++i)
        t[y + 8 * i][x] = W[(size_t)(k0 + y + 8 * i) * N + n0 + x];
    __syncthreads();
#pragma unroll
    for (int i = 0; i < 4; ++i)
        Th[(size_t)(n0 + y + 8 * i) * Kd + k0 + x] = h16bits(t[x][y + 8 * i]);
}

// Wa,Wb [D,16] -> [32, D] fp16 (rows 0-15 = Wa^T, 16-31 = Wb^T)
__global__ void transpose_ab_kernel(const float* __restrict__ Wa,
                                    const float* __restrict__ Wb,
                                    u16* __restrict__ T) {
    int n = blockIdx.y;
    int k = blockIdx.x * 256 + threadIdx.x;
    const float* W = (n < 16) ? Wa : Wb;
    T[(size_t)n * Dc + k] = h16bits(W[(size_t)k * Hc + (n & 15)]);
}

// ---------------- HMMA GEMM: C[M,N] = A[M,K] @ Bt[N,K]^T ----------------
// Plain fp16 x fp16, fp32 accumulate. 256 threads = 8 warps (4m x 2n).
// BK=64, 3-stage cp.async pipeline, occupancy 2.
template <int BN>
__global__ __launch_bounds__(256, 2)
void mma_gemm(const u16* __restrict__ A, const u16* __restrict__ Bt,
              float* __restrict__ C, int M, int N, int Kd) {
    extern __shared__ __align__(1024) char smem[];
    constexpr int ATILE = 128 * 128;          // 16 KB
    constexpr int BTILE = BN * 128;
    constexpr int STAGE = ATILE + BTILE;
    constexpr int WN = BN / 2;                // warp n-tile
    constexpr int NG = WN / 16;               // ldmatrix.x4 groups per k16
    const int tid = threadIdx.x, lane = tid & 31, wid = tid >> 5;
    const int wm = (wid & 3) * 32;
    const int wn = (wid >> 2) * WN;
    const int m0 = blockIdx.y * 128, n0 = blockIdx.x * BN;
    const int ktiles = Kd >> 6;
    const u32 sb = smem_u32(smem);

    const u16* Ag = A + (size_t)m0 * Kd;
    const u16* Bg = Bt + (size_t)n0 * Kd;

    auto issue = [&](int kt) {
        const int ko = kt << 6;
        const u32 st = sb + (u32)(kt % 3) * STAGE;
        for (int c = tid; c < 128 * 8; c += 256) {
            int rr = c >> 3, u = c & 7;
            cp16(st + SWZ(rr * 128 + u * 16), Ag + (size_t)rr * Kd + ko + u * 8);
        }
        for (int c = tid; c < BN * 8; c += 256) {
            int rr = c >> 3, u = c & 7;
            cp16(st + ATILE + SWZ(rr * 128 + u * 16), Bg + (size_t)rr * Kd + ko + u * 8);
        }
    };

    float acc[2][WN / 8][4];
#pragma unroll
    for (int i = 0; i < 2; ++i)
#pragma unroll
        for (int j = 0; j < WN / 8; ++j)
#pragma unroll
            for (int l = 0; l < 4; ++l) acc[i][j][l] = 0.f;

    issue(0);
    asm volatile("cp.async.commit_group;");
    issue(1);
    asm volatile("cp.async.commit_group;");

    for (int kt = 0; kt < ktiles; ++kt) {
        asm volatile("cp.async.wait_group 1;" ::: "memory");
        __syncthreads();
        if (kt + 2 < ktiles) issue(kt + 2);
        asm volatile("cp.async.commit_group;");

        const u32 Ab = sb + (u32)(kt % 3) * STAGE;
        const u32 Bb = Ab + ATILE;
#pragma unroll
        for (int ks = 0; ks < 4; ++ks) {
            u32 ah[2][4], bh[NG][4];
            const int arow = wm + (lane & 15);
            const int acol = ks * 32 + ((lane >> 4) << 4);
#pragma unroll
            for (int mf = 0; mf < 2; ++mf)
                ldsm4(ah[mf], Ab + SWZ((arow + mf * 16) * 128 + acol));
            const int brow = wn + (lane & 7) + ((lane >> 4) << 3);
            const int bcol = ks * 32 + ((lane & 8) << 1);
#pragma unroll
            for (int g = 0; g < NG; ++g)
                ldsm4(bh[g], Bb + SWZ((brow + g * 16) * 128 + bcol));
#pragma unroll
            for (int mf = 0; mf < 2; ++mf)
#pragma unroll
                for (int g = 0; g < NG; ++g) {
                    mma16816(acc[mf][2 * g + 0], ah[mf], &bh[g][0]);
                    mma16816(acc[mf][2 * g + 1], ah[mf], &bh[g][2]);
                }
        }
    }

    // epilogue: direct gmem stores
#pragma unroll
    for (int mf = 0; mf < 2; ++mf)
#pragma unroll
        for (int f = 0; f < WN / 8; ++f) {
            int row = m0 + wm + mf * 16 + (lane >> 2);
            int col = n0 + wn + f * 8 + (lane & 3) * 2;
            float2 lo2, hi2;
            lo2.x = acc[mf][f][0]; lo2.y = acc[mf][f][1];
            hi2.x = acc[mf][f][2]; hi2.y = acc[mf][f][3];
            *(float2*)&C[(size_t)row * N + col] = lo2;
            *(float2*)&C[(size_t)(row + 8) * N + col] = hi2;
        }
}

// ---------------- depthwise causal conv (K=4) + silu ----------------
__global__ void conv_silu_kernel(const float* __restrict__ mixed,
                                 const float* __restrict__ cw,
                                 float* __restrict__ out) {
    const int c  = blockIdx.x * 128 + threadIdx.x;
    const int b  = blockIdx.z;
    const int t0 = blockIdx.y * 256;
    const float w0 = cw[c * 4 + 0], w1 = cw[c * 4 + 1];
    const float w2 = cw[c * 4 + 2], w3 = cw[c * 4 + 3];
    const float* base  = mixed + (size_t)b * Tc * CONVD + c;
    float*       obase = out   + (size_t)b * Tc * CONVD + c;
    float xm3 = (t0 >= 3) ? base[(size_t)(t0 - 3) * CONVD] : 0.f;
    float xm2 = (t0 >= 2) ? base[(size_t)(t0 - 2) * CONVD] : 0.f;
    float xm1 = (t0 >= 1) ? base[(size_t)(t0 - 1) * CONVD] : 0.f;
#pragma unroll 4
    for (int t = t0; t < t0 + 256; ++t) {
        float x = base[(size_t)t * CONVD];
        float y = w0 * xm3 + w1 * xm2 + w2 * xm1 + w3 * x;
        float s = 1.f / (1.f + expf(-y));
        obase[(size_t)t * CONVD] = y * s;
        xm3 = xm2; xm2 = xm1; xm1 = x;
    }
}

// ---------------- per-head L2 norm for q and k (in place) ----------------
__global__ void l2norm_kernel(float* __restrict__ qkv) {
    const int warp = threadIdx.x >> 5, lane = threadIdx.x & 31;
    const int vec = blockIdx.x * 8 + warp;      // [0, 2*BT*H)
    const int qk = vec >> 16;                   // BT*H == 65536
    const int r  = vec & 65535;
    const int bt = r >> 4, h = r & 15;
    float* p = qkv + (size_t)bt * CONVD + qk * KEYD + h * 128 + lane * 4;
    float4 v = *(float4*)p;
    float ss = v.x * v.x + v.y * v.y + v.z * v.z + v.w * v.w;
#pragma unroll
    for (int off = 16; off; off >>= 1) ss += __shfl_xor_sync(~0u, ss, off);
    float scale = rsqrtf(ss + 1e-6f);
    if (qk == 0) scale *= 0.08838834764831845f;   // DK^-0.5
    v.x *= scale; v.y *= scale; v.z *= scale; v.w *= scale;
    *(float4*)p = v;
}

// ---------------- a/b activation ----------------
__global__ void ab_act_kernel(const float* __restrict__ Cab,
                              const float* __restrict__ dt_bias,
                              const float* __restrict__ A_log,
                              float* __restrict__ gb) {
    int i = blockIdx.x * 256 + threadIdx.x;     // over BT*16
    int m = i >> 4, h = i & 15;
    float av = Cab[(size_t)m * 32 + h];
    float bv = Cab[(size_t)m * 32 + 16 + h];
    float x = av + dt_bias[h];
    float sp = (x > 20.f) ? x : log1pf(expf(x));
    gb[i] = -expf(A_log[h]) * sp;
    gb[(size_t)BT * Hc + i] = 1.f / (1.f + expf(-bv));
}

// ---------------- gated delta rule scan (single merged reduction tree) ----------
__global__ __launch_bounds__(256, 1)
void scan_kernel(const float* __restrict__ qkv, const float* __restrict__ gb,
                 float* __restrict__ od) {
    const int blk  = blockIdx.x;
    const int vblk = blk & 3;
    const int h    = (blk >> 2) & 15;
    const int b    = blk >> 6;
    const int tid = threadIdx.x;
    const int tk = tid & 15, tv = tid >> 4;
    const int vbase = vblk * 32 + tv * 2;

    const float* qp = qkv + (size_t)b * Tc * CONVD + h * 128 + tk * 8;
    const float* kp = qp + KEYD;
    const float* vp = qkv + (size_t)b * Tc * CONVD + 2 * KEYD + h * 128 + vbase;
    const float* gp = gb + (size_t)b * Tc * Hc + h;
    const float* bp = gp + (size_t)BT * Hc;
    float* op = od + ((size_t)b * Tc * Hc + h) * 128 + vbase;

    float S[8][2];
#pragma unroll
    for (int i = 0; i < 8; ++i) { S[i][0] = 0.f; S[i][1] = 0.f; }

    for (int t = 0; t < Tc; ++t) {
        float4 q0 = *(const float4*)qp, q1 = *(const float4*)(qp + 4);
        float4 k0 = *(const float4*)kp, k1 = *(const float4*)(kp + 4);
        float2 vv = *(const float2*)vp;
        float gg = *gp, bb = *bp;
        float eg = __expf(gg);
        float kr[8] = {k0.x, k0.y, k0.z, k0.w, k1.x, k1.y, k1.z, k1.w};
        float qr[8] = {q0.x, q0.y, q0.z, q0.w, q1.x, q1.y, q1.z, q1.w};

        float ks0 = 0.f, ks1 = 0.f, qs0 = 0.f, qs1 = 0.f, qk = 0.f;
#pragma unroll
        for (int i = 0; i < 8; ++i) {
            ks0 = fmaf(kr[i], S[i][0], ks0);
            ks1 = fmaf(kr[i], S[i][1], ks1);
            qs0 = fmaf(qr[i], S[i][0], qs0);
            qs1 = fmaf(qr[i], S[i][1], qs1);
            qk  = fmaf(qr[i], kr[i], qk);
        }
#pragma unroll
        for (int off = 8; off; off >>= 1) {
            ks0 += __shfl_xor_sync(~0u, ks0, off);
            ks1 += __shfl_xor_sync(~0u, ks1, off);
            qs0 += __shfl_xor_sync(~0u, qs0, off);
            qs1 += __shfl_xor_sync(~0u, qs1, off);
            qk  += __shfl_xor_sync(~0u, qk, off);
        }
        float d0 = (vv.x - eg * ks0) * bb;
        float d1 = (vv.y - eg * ks1) * bb;
        if (tk == 0) {
            float2 ov;
            ov.x = fmaf(qk, d0, eg * qs0);
            ov.y = fmaf(qk, d1, eg * qs1);
            *(float2*)op = ov;
        }
#pragma unroll
        for (int i = 0; i < 8; ++i) {
            S[i][0] = fmaf(kr[i], d0, eg * S[i][0]);
            S[i][1] = fmaf(kr[i], d1, eg * S[i][1]);
        }
        qp += CONVD; kp += CONVD; vp += CONVD;
        gp += Hc; bp += Hc;
        op += (size_t)Hc * 128;
    }
}

// ---------------- gated RMSNorm -> fp16 ----------------
__global__ void gate_norm_kernel(const float* __restrict__ od,
                                 const float* __restrict__ z,
                                 const float* __restrict__ nw,
                                 ushort4* __restrict__ y) {
    const int warp = threadIdx.x >> 5, lane = threadIdx.x & 31;
    const int vec = blockIdx.x * 8 + warp;      // bt*H + h
    const float* opv = od + (size_t)vec * 128 + lane * 4;
    const float* zpv = z  + (size_t)vec * 128 + lane * 4;
    float4 o  = *(const float4*)opv;
    float4 zz = *(const float4*)zpv;
    float4 og;
    og.x = o.x * (zz.x / (1.f + expf(-zz.x)));
    og.y = o.y * (zz.y / (1.f + expf(-zz.y)));
    og.z = o.z * (zz.z / (1.f + expf(-zz.z)));
    og.w = o.w * (zz.w / (1.f + expf(-zz.w)));
    float ss = og.x * og.x + og.y * og.y + og.z * og.z + og.w * og.w;
#pragma unroll
    for (int off = 16; off; off >>= 1) ss += __shfl_xor_sync(~0u, ss, off);
    float r = rsqrtf(ss * (1.f / 128.f) + 1e-6f);
    float4 w = *(const float4*)&nw[lane * 4];
    ushort4 H;
    H.x = h16bits(og.x * r * w.x);
    H.y = h16bits(og.y * r * w.y);
    H.z = h16bits(og.z * r * w.z);
    H.w = h16bits(og.w * r * w.w);
    y[(size_t)vec * 32 + lane] = H;
}

// ---------------- launch ----------------
extern "C" void kernel_launch(void* const* d_in, const int* in_sizes, int n_in,
                              void* d_out, int out_size) {
    const float* hs      = (const float*)d_in[0];
    const float* W_qkv   = (const float*)d_in[1];
    const float* conv_w  = (const float*)d_in[2];
    const float* W_z     = (const float*)d_in[3];
    const float* W_b     = (const float*)d_in[4];
    const float* W_a     = (const float*)d_in[5];
    const float* dt_bias = (const float*)d_in[6];
    const float* A_log   = (const float*)d_in[7];
    const float* norm_w  = (const float*)d_in[8];
    const float* W_out   = (const float*)d_in[9];
    float* out = (float*)d_out;

    float *mixed, *qkv, *gb, *z, *od, *Cab;
    u16 *hsA, *Wq, *Wz, *Wo, *ab, *y;
    cudaGetSymbolAddress((void**)&mixed, g_mixed);
    cudaGetSymbolAddress((void**)&qkv,   g_qkv);
    cudaGetSymbolAddress((void**)&gb,    g_gb);
    cudaGetSymbolAddress((void**)&z,     g_z);
    cudaGetSymbolAddress((void**)&od,    g_od);
    cudaGetSymbolAddress((void**)&Cab,   g_Cab);
    cudaGetSymbolAddress((void**)&hsA,   g_hsA);
    cudaGetSymbolAddress((void**)&Wq,    g_Wq);
    cudaGetSymbolAddress((void**)&Wz,    g_Wz);
    cudaGetSymbolAddress((void**)&Wo,    g_Wo);
    cudaGetSymbolAddress((void**)&ab,    g_ab);
    cudaGetSymbolAddress((void**)&y,     g_y);

    const int smem128 = 3 * (16384 + 128 * 128);   // 98304
    const int smem32  = 3 * (16384 + 32 * 128);    // 61440
    cudaFuncSetAttribute(mma_gemm<128>, cudaFuncAttributeMaxDynamicSharedMemorySize, smem128);
    cudaFuncSetAttribute(mma_gemm<32>,  cudaFuncAttributeMaxDynamicSharedMemorySize, smem32);

    // operand prep
    cvt_h16_kernel<<<(BT * Dc / 4 + 255) / 256, 256>>>(
        (const float4*)hs, (ushort4*)hsA, BT * Dc / 4);
    transpose_cvt_kernel<<<dim3(CONVD / 32, Dc / 32), dim3(32, 8)>>>(W_qkv, Wq, Dc, CONVD);
    transpose_cvt_kernel<<<dim3(VALD / 32, Dc / 32), dim3(32, 8)>>>(W_z, Wz, Dc, VALD);
    transpose_cvt_kernel<<<dim3(Dc / 32, VALD / 32), dim3(32, 8)>>>(W_out, Wo, VALD, Dc);
    transpose_ab_kernel<<<dim3(Dc / 256, 32), 256>>>(W_a, W_b, ab);

    // 1. mixed = hs @ W_qkv
    mma_gemm<128><<<dim3(CONVD / 128, BT / 128), 256, smem128>>>(
        hsA, Wq, mixed, BT, CONVD, Dc);
    // 2. depthwise causal conv + silu
    conv_silu_kernel<<<dim3(CONVD / 128, Tc / 256, Bc), 128>>>(mixed, conv_w, qkv);
    // 3. l2norm q, k
    l2norm_kernel<<<(2 * BT * Hc) / 8, 256>>>(qkv);
    // 4. a/b projection (N=32 GEMM) + activations
    mma_gemm<32><<<dim3(1, BT / 128), 256, smem32>>>(hsA, ab, Cab, BT, 32, Dc);
    ab_act_kernel<<<(BT * Hc) / 256, 256>>>(Cab, dt_bias, A_log, gb);
    // 5. z = hs @ W_z
    mma_gemm<128><<<dim3(VALD / 128, BT / 128), 256, smem128>>>(
        hsA, Wz, z, BT, VALD, Dc);
    // 6. gated delta rule scan
    scan_kernel<<<Bc * Hc * 4, 256>>>(qkv, gb, od);
    // 7. gated RMSNorm -> y fp16
    gate_norm_kernel<<<(BT * Hc) / 8, 256>>>(od, z, norm_w, (ushort4*)y);
    // 8. out = y @ W_out
    mma_gemm<128><<<dim3(Dc / 128, BT / 128), 256, smem128>>>(
        y, Wo, out, BT, Dc, Dc);
}

// round 9
// speedup vs baseline: 1.2104x; 1.0046x over previous
#include <cuda_runtime.h>
#include <cuda_fp16.h>
#include <cstdint>
#include <cstddef>

#define Bc    2
#define Tc    2048
#define Dc    2048
#define Hc    16
#define KEYD  2048
#define VALD  2048
#define CONVD 6144
#define BT    4096   // B*T

typedef unsigned short u16;
typedef uint32_t u32;

// ---------------- scratch (device globals: allocation-free) ----------------
__device__ float g_mixed[(size_t)BT * CONVD];   // qkv pre-conv (fp32)
__device__ float g_qkv[(size_t)BT * CONVD];     // post conv+silu (+l2norm in place)
__device__ float g_gb[2 * BT * Hc];             // g then beta
__device__ float g_z[(size_t)BT * VALD];
__device__ float g_od[(size_t)BT * VALD];       // delta-rule output
__device__ float g_Cab[(size_t)BT * 32];        // a/b projection pre-activation

// fp16 operands
__device__ u16 g_hsA[(size_t)BT * Dc];
__device__ u16 g_Wq[(size_t)CONVD * Dc];
__device__ u16 g_Wz[(size_t)VALD * Dc];
__device__ u16 g_Wo[(size_t)Dc * VALD];
__device__ u16 g_ab[(size_t)32 * Dc];
__device__ u16 g_y[(size_t)BT * VALD];

// ---------------- helpers ----------------
__device__ __forceinline__ u16 h16bits(float x) {
    __half h = __float2half_rn(x);
    return *reinterpret_cast<u16*>(&h);
}
__device__ __forceinline__ u32 smem_u32(const void* p) {
    u32 a;
    asm("{ .reg .u64 t; cvta.to.shared.u64 t, %1; cvt.u32.u64 %0, t; }" : "=r"(a) : "l"(p));
    return a;
}
#define SWZ(x) ((x) ^ (((x) >> 3) & 0x70))

__device__ __forceinline__ void cp16(u32 s, const void* g) {
    asm volatile("cp.async.cg.shared.global [%0], [%1], 16;" :: "r"(s), "l"(g));
}
__device__ __forceinline__ void ldsm4(u32* r, u32 a) {
    asm volatile("ldmatrix.sync.aligned.m8n8.x4.shared.b16 {%0,%1,%2,%3}, [%4];"
                 : "=r"(r[0]), "=r"(r[1]), "=r"(r[2]), "=r"(r[3]) : "r"(a));
}
__device__ __forceinline__ void mma16816(float* c, const u32* a, const u32* b) {
    asm volatile(
        "mma.sync.aligned.m16n8k16.row.col.f32.f16.f16.f32 "
        "{%0,%1,%2,%3}, {%4,%5,%6,%7}, {%8,%9}, {%0,%1,%2,%3};"
        : "+f"(c[0]), "+f"(c[1]), "+f"(c[2]), "+f"(c[3])
        : "r"(a[0]), "r"(a[1]), "r"(a[2]), "r"(a[3]), "r"(b[0]), "r"(b[1]));
}

// ---------------- operand conversion kernels ----------------
__global__ void cvt_h16_kernel(const float4* __restrict__ in,
                               ushort4* __restrict__ out, int n4) {
    int i = blockIdx.x * 256 + threadIdx.x;
    if (i >= n4) return;
    float4 v = in[i];
    ushort4 H;
    H.x = h16bits(v.x); H.y = h16bits(v.y);
    H.z = h16bits(v.z); H.w = h16bits(v.w);
    out[i] = H;
}

// transpose + fp16 convert: W [Kd, N] fp32 -> T [N, Kd] fp16
__global__ void transpose_cvt_kernel(const float* __restrict__ W,
                                     u16* __restrict__ Th, int Kd, int N) {
    __shared__ float t[32][33];
    int n0 = blockIdx.x * 32, k0 = blockIdx.y * 32;
    int x = threadIdx.x, y = threadIdx.y;   // 32 x 8
#pragma unroll
    for (int i = 0; i < 4; ++i)
        t[y + 8 * i][x] = W[(size_t)(k0 + y + 8 * i) * N + n0 + x];
    __syncthreads();
#pragma unroll
    for (int i = 0; i < 4; ++i)
        Th[(size_t)(n0 + y + 8 * i) * Kd + k0 + x] = h16bits(t[x][y + 8 * i]);
}

// Wa,Wb [D,16] -> [32, D] fp16 (rows 0-15 = Wa^T, 16-31 = Wb^T)
__global__ void transpose_ab_kernel(const float* __restrict__ Wa,
                                    const float* __restrict__ Wb,
                                    u16* __restrict__ T) {
    int n = blockIdx.y;
    int k = blockIdx.x * 256 + threadIdx.x;
    const float* W = (n < 16) ? Wa : Wb;
    T[(size_t)n * Dc + k] = h16bits(W[(size_t)k * Hc + (n & 15)]);
}

// ---------------- HMMA GEMM: C[M,N] = A[M,K] @ Bt[N,K]^T ----------------
// fp16 x fp16, fp32 accumulate. 256 threads = 8 warps.
// BN=256: warp grid 2m x 4n, warp tile 64x64 (high smem reuse: 16 MAC/B).
// BN=32 : warp grid 4m x 2n, warp tile 32x16 (small-N path).
// BK=64, 3-stage cp.async pipeline.
template <int BN>
__global__ __launch_bounds__(256, 1)
void mma_gemm(const u16* __restrict__ A, const u16* __restrict__ Bt,
              float* __restrict__ C, int M, int N, int Kd) {
    extern __shared__ __align__(1024) char smem[];
    constexpr int ATILE = 128 * 128;          // 16 KB
    constexpr int BTILE = BN * 128;
    constexpr int STAGE = ATILE + BTILE;
    constexpr int WMW = (BN == 256) ? 64 : 32;    // warp m tile
    constexpr int WN  = (BN == 256) ? 64 : 16;    // warp n tile
    constexpr int WARPS_M = 128 / WMW;
    constexpr int MF = WMW / 16;
    constexpr int NG = WN / 16;
    const int tid = threadIdx.x, lane = tid & 31, wid = tid >> 5;
    const int wm = (wid % WARPS_M) * WMW;
    const int wn = (wid / WARPS_M) * WN;
    const int m0 = blockIdx.y * 128, n0 = blockIdx.x * BN;
    const int ktiles = Kd >> 6;
    const u32 sb = smem_u32(smem);

    const u16* Ag = A + (size_t)m0 * Kd;
    const u16* Bg = Bt + (size_t)n0 * Kd;

    auto issue = [&](int kt) {
        const int ko = kt << 6;
        const u32 st = sb + (u32)(kt % 3) * STAGE;
        for (int c = tid; c < 128 * 8; c += 256) {
            int rr = c >> 3, u = c & 7;
            cp16(st + SWZ(rr * 128 + u * 16), Ag + (size_t)rr * Kd + ko + u * 8);
        }
        for (int c = tid; c < BN * 8; c += 256) {
            int rr = c >> 3, u = c & 7;
            cp16(st + ATILE + SWZ(rr * 128 + u * 16), Bg + (size_t)rr * Kd + ko + u * 8);
        }
    };

    float acc[MF][WN / 8][4];
#pragma unroll
    for (int i = 0; i < MF; ++i)
#pragma unroll
        for (int j = 0; j < WN / 8; ++j)
#pragma unroll
            for (int l = 0; l < 4; ++l) acc[i][j][l] = 0.f;

    issue(0);
    asm volatile("cp.async.commit_group;");
    issue(1);
    asm volatile("cp.async.commit_group;");

    for (int kt = 0; kt < ktiles; ++kt) {
        asm volatile("cp.async.wait_group 1;" ::: "memory");
        __syncthreads();
        if (kt + 2 < ktiles) issue(kt + 2);
        asm volatile("cp.async.commit_group;");

        const u32 Ab = sb + (u32)(kt % 3) * STAGE;
        const u32 Bb = Ab + ATILE;
#pragma unroll
        for (int ks = 0; ks < 4; ++ks) {
            u32 ah[MF][4], bh[NG][4];
            const int arow = wm + (lane & 15);
            const int acol = ks * 32 + ((lane >> 4) << 4);
#pragma unroll
            for (int mf = 0; mf < MF; ++mf)
                ldsm4(ah[mf], Ab + SWZ((arow + mf * 16) * 128 + acol));
            const int brow = wn + (lane & 7) + ((lane >> 4) << 3);
            const int bcol = ks * 32 + ((lane & 8) << 1);
#pragma unroll
            for (int g = 0; g < NG; ++g)
                ldsm4(bh[g], Bb + SWZ((brow + g * 16) * 128 + bcol));
#pragma unroll
            for (int mf = 0; mf < MF; ++mf)
#pragma unroll
                for (int g = 0; g < NG; ++g) {
                    mma16816(acc[mf][2 * g + 0], ah[mf], &bh[g][0]);
                    mma16816(acc[mf][2 * g + 1], ah[mf], &bh[g][2]);
                }
        }
    }

    // epilogue: direct gmem stores
#pragma unroll
    for (int mf = 0; mf < MF; ++mf)
#pragma unroll
        for (int f = 0; f < WN / 8; ++f) {
            int row = m0 + wm + mf * 16 + (lane >> 2);
            int col = n0 + wn + f * 8 + (lane & 3) * 2;
            float2 lo2, hi2;
            lo2.x = acc[mf][f][0]; lo2.y = acc[mf][f][1];
            hi2.x = acc[mf][f][2]; hi2.y = acc[mf][f][3];
            *(float2*)&C[(size_t)row * N + col] = lo2;
            *(float2*)&C[(size_t)(row + 8) * N + col] = hi2;
        }
}

// ---------------- depthwise causal conv (K=4) + silu ----------------
__global__ void conv_silu_kernel(const float* __restrict__ mixed,
                                 const float* __restrict__ cw,
                                 float* __restrict__ out) {
    const int c  = blockIdx.x * 128 + threadIdx.x;
    const int b  = blockIdx.z;
    const int t0 = blockIdx.y * 256;
    const float w0 = cw[c * 4 + 0], w1 = cw[c * 4 + 1];
    const float w2 = cw[c * 4 + 2], w3 = cw[c * 4 + 3];
    const float* base  = mixed + (size_t)b * Tc * CONVD + c;
    float*       obase = out   + (size_t)b * Tc * CONVD + c;
    float xm3 = (t0 >= 3) ? base[(size_t)(t0 - 3) * CONVD] : 0.f;
    float xm2 = (t0 >= 2) ? base[(size_t)(t0 - 2) * CONVD] : 0.f;
    float xm1 = (t0 >= 1) ? base[(size_t)(t0 - 1) * CONVD] : 0.f;
#pragma unroll 4
    for (int t = t0; t < t0 + 256; ++t) {
        float x = base[(size_t)t * CONVD];
        float y = w0 * xm3 + w1 * xm2 + w2 * xm1 + w3 * x;
        float s = 1.f / (1.f + expf(-y));
        obase[(size_t)t * CONVD] = y * s;
        xm3 = xm2; xm2 = xm1; xm1 = x;
    }
}

// ---------------- per-head L2 norm for q and k (in place) ----------------
__global__ void l2norm_kernel(float* __restrict__ qkv) {
    const int warp = threadIdx.x >> 5, lane = threadIdx.x & 31;
    const int vec = blockIdx.x * 8 + warp;      // [0, 2*BT*H)
    const int qk = vec >> 16;                   // BT*H == 65536
    const int r  = vec & 65535;
    const int bt = r >> 4, h = r & 15;
    float* p = qkv + (size_t)bt * CONVD + qk * KEYD + h * 128 + lane * 4;
    float4 v = *(float4*)p;
    float ss = v.x * v.x + v.y * v.y + v.z * v.z + v.w * v.w;
#pragma unroll
    for (int off = 16; off; off >>= 1) ss += __shfl_xor_sync(~0u, ss, off);
    float scale = rsqrtf(ss + 1e-6f);
    if (qk == 0) scale *= 0.08838834764831845f;   // DK^-0.5
    v.x *= scale; v.y *= scale; v.z *= scale; v.w *= scale;
    *(float4*)p = v;
}

// ---------------- a/b activation ----------------
__global__ void ab_act_kernel(const float* __restrict__ Cab,
                              const float* __restrict__ dt_bias,
                              const float* __restrict__ A_log,
                              float* __restrict__ gb) {
    int i = blockIdx.x * 256 + threadIdx.x;     // over BT*16
    int m = i >> 4, h = i & 15;
    float av = Cab[(size_t)m * 32 + h];
    float bv = Cab[(size_t)m * 32 + 16 + h];
    float x = av + dt_bias[h];
    float sp = (x > 20.f) ? x : log1pf(expf(x));
    gb[i] = -expf(A_log[h]) * sp;
    gb[(size_t)BT * Hc + i] = 1.f / (1.f + expf(-bv));
}

// ---------------- gated delta rule scan (single merged reduction tree) ----------
__global__ __launch_bounds__(256, 1)
void scan_kernel(const float* __restrict__ qkv, const float* __restrict__ gb,
                 float* __restrict__ od) {
    const int blk  = blockIdx.x;
    const int vblk = blk & 3;
    const int h    = (blk >> 2) & 15;
    const int b    = blk >> 6;
    const int tid = threadIdx.x;
    const int tk = tid & 15, tv = tid >> 4;
    const int vbase = vblk * 32 + tv * 2;

    const float* qp = qkv + (size_t)b * Tc * CONVD + h * 128 + tk * 8;
    const float* kp = qp + KEYD;
    const float* vp = qkv + (size_t)b * Tc * CONVD + 2 * KEYD + h * 128 + vbase;
    const float* gp = gb + (size_t)b * Tc * Hc + h;
    const float* bp = gp + (size_t)BT * Hc;
    float* op = od + ((size_t)b * Tc * Hc + h) * 128 + vbase;

    float S[8][2];
#pragma unroll
    for (int i = 0; i < 8; ++i) { S[i][0] = 0.f; S[i][1] = 0.f; }

    for (int t = 0; t < Tc; ++t) {
        float4 q0 = *(const float4*)qp, q1 = *(const float4*)(qp + 4);
        float4 k0 = *(const float4*)kp, k1 = *(const float4*)(kp + 4);
        float2 vv = *(const float2*)vp;
        float gg = *gp, bb = *bp;
        float eg = __expf(gg);
        float kr[8] = {k0.x, k0.y, k0.z, k0.w, k1.x, k1.y, k1.z, k1.w};
        float qr[8] = {q0.x, q0.y, q0.z, q0.w, q1.x, q1.y, q1.z, q1.w};

        float ks0 = 0.f, ks1 = 0.f, qs0 = 0.f, qs1 = 0.f, qk = 0.f;
#pragma unroll
        for (int i = 0; i < 8; ++i) {
            ks0 = fmaf(kr[i], S[i][0], ks0);
            ks1 = fmaf(kr[i], S[i][1], ks1);
            qs0 = fmaf(qr[i], S[i][0], qs0);
            qs1 = fmaf(qr[i], S[i][1], qs1);
            qk  = fmaf(qr[i], kr[i], qk);
        }
#pragma unroll
        for (int off = 8; off; off >>= 1) {
            ks0 += __shfl_xor_sync(~0u, ks0, off);
            ks1 += __shfl_xor_sync(~0u, ks1, off);
            qs0 += __shfl_xor_sync(~0u, qs0, off);
            qs1 += __shfl_xor_sync(~0u, qs1, off);
            qk  += __shfl_xor_sync(~0u, qk, off);
        }
        float d0 = (vv.x - eg * ks0) * bb;
        float d1 = (vv.y - eg * ks1) * bb;
        if (tk == 0) {
            float2 ov;
            ov.x = fmaf(qk, d0, eg * qs0);
            ov.y = fmaf(qk, d1, eg * qs1);
            *(float2*)op = ov;
        }
#pragma unroll
        for (int i = 0; i < 8; ++i) {
            S[i][0] = fmaf(kr[i], d0, eg * S[i][0]);
            S[i][1] = fmaf(kr[i], d1, eg * S[i][1]);
        }
        qp += CONVD; kp += CONVD; vp += CONVD;
        gp += Hc; bp += Hc;
        op += (size_t)Hc * 128;
    }
}

// ---------------- gated RMSNorm -> fp16 ----------------
__global__ void gate_norm_kernel(const float* __restrict__ od,
                                 const float* __restrict__ z,
                                 const float* __restrict__ nw,
                                 ushort4* __restrict__ y) {
    const int warp = threadIdx.x >> 5, lane = threadIdx.x & 31;
    const int vec = blockIdx.x * 8 + warp;      // bt*H + h
    const float* opv = od + (size_t)vec * 128 + lane * 4;
    const float* zpv = z  + (size_t)vec * 128 + lane * 4;
    float4 o  = *(const float4*)opv;
    float4 zz = *(const float4*)zpv;
    float4 og;
    og.x = o.x * (zz.x / (1.f + expf(-zz.x)));
    og.y = o.y * (zz.y / (1.f + expf(-zz.y)));
    og.z = o.z * (zz.z / (1.f + expf(-zz.z)));
    og.w = o.w * (zz.w / (1.f + expf(-zz.w)));
    float ss = og.x * og.x + og.y * og.y + og.z * og.z + og.w * og.w;
#pragma unroll
    for (int off = 16; off; off >>= 1) ss += __shfl_xor_sync(~0u, ss, off);
    float r = rsqrtf(ss * (1.f / 128.f) + 1e-6f);
    float4 w = *(const float4*)&nw[lane * 4];
    ushort4 H;
    H.x = h16bits(og.x * r * w.x);
    H.y = h16bits(og.y * r * w.y);
    H.z = h16bits(og.z * r * w.z);
    H.w = h16bits(og.w * r * w.w);
    y[(size_t)vec * 32 + lane] = H;
}

// ---------------- launch ----------------
extern "C" void kernel_launch(void* const* d_in, const int* in_sizes, int n_in,
                              void* d_out, int out_size) {
    const float* hs      = (const float*)d_in[0];
    const float* W_qkv   = (const float*)d_in[1];
    const float* conv_w  = (const float*)d_in[2];
    const float* W_z     = (const float*)d_in[3];
    const float* W_b     = (const float*)d_in[4];
    const float* W_a     = (const float*)d_in[5];
    const float* dt_bias = (const float*)d_in[6];
    const float* A_log   = (const float*)d_in[7];
    const float* norm_w  = (const float*)d_in[8];
    const float* W_out   = (const float*)d_in[9];
    float* out = (float*)d_out;

    float *mixed, *qkv, *gb, *z, *od, *Cab;
    u16 *hsA, *Wq, *Wz, *Wo, *ab, *y;
    cudaGetSymbolAddress((void**)&mixed, g_mixed);
    cudaGetSymbolAddress((void**)&qkv,   g_qkv);
    cudaGetSymbolAddress((void**)&gb,    g_gb);
    cudaGetSymbolAddress((void**)&z,     g_z);
    cudaGetSymbolAddress((void**)&od,    g_od);
    cudaGetSymbolAddress((void**)&Cab,   g_Cab);
    cudaGetSymbolAddress((void**)&hsA,   g_hsA);
    cudaGetSymbolAddress((void**)&Wq,    g_Wq);
    cudaGetSymbolAddress((void**)&Wz,    g_Wz);
    cudaGetSymbolAddress((void**)&Wo,    g_Wo);
    cudaGetSymbolAddress((void**)&ab,    g_ab);
    cudaGetSymbolAddress((void**)&y,     g_y);

    const int smem256 = 3 * (16384 + 256 * 128);   // 147456
    const int smem32  = 3 * (16384 + 32 * 128);    // 61440
    cudaFuncSetAttribute(mma_gemm<256>, cudaFuncAttributeMaxDynamicSharedMemorySize, smem256);
    cudaFuncSetAttribute(mma_gemm<32>,  cudaFuncAttributeMaxDynamicSharedMemorySize, smem32);

    // operand prep
    cvt_h16_kernel<<<(BT * Dc / 4 + 255) / 256, 256>>>(
        (const float4*)hs, (ushort4*)hsA, BT * Dc / 4);
    transpose_cvt_kernel<<<dim3(CONVD / 32, Dc / 32), dim3(32, 8)>>>(W_qkv, Wq, Dc, CONVD);
    transpose_cvt_kernel<<<dim3(VALD / 32, Dc / 32), dim3(32, 8)>>>(W_z, Wz, Dc, VALD);
    transpose_cvt_kernel<<<dim3(Dc / 32, VALD / 32), dim3(32, 8)>>>(W_out, Wo, VALD, Dc);
    transpose_ab_kernel<<<dim3(Dc / 256, 32), 256>>>(W_a, W_b, ab);

    // 1. mixed = hs @ W_qkv
    mma_gemm<256><<<dim3(CONVD / 256, BT / 128), 256, smem256>>>(
        hsA, Wq, mixed, BT, CONVD, Dc);
    // 2. depthwise causal conv + silu
    conv_silu_kernel<<<dim3(CONVD / 128, Tc / 256, Bc), 128>>>(mixed, conv_w, qkv);
    // 3. l2norm q, k
    l2norm_kernel<<<(2 * BT * Hc) / 8, 256>>>(qkv);
    // 4. a/b projection (N=32 GEMM) + activations
    mma_gemm<32><<<dim3(1, BT / 128), 256, smem32>>>(hsA, ab, Cab, BT, 32, Dc);
    ab_act_kernel<<<(BT * Hc) / 256, 256>>>(Cab, dt_bias, A_log, gb);
    // 5. z = hs @ W_z
    mma_gemm<256><<<dim3(VALD / 256, BT / 128), 256, smem256>>>(
        hsA, Wz, z, BT, VALD, Dc);
    // 6. gated delta rule scan
    scan_kernel<<<Bc * Hc * 4, 256>>>(qkv, gb, od);
    // 7. gated RMSNorm -> y fp16
    gate_norm_kernel<<<(BT * Hc) / 8, 256>>>(od, z, norm_w, (ushort4*)y);
    // 8. out = y @ W_out
    mma_gemm<256><<<dim3(Dc / 256, BT / 128), 256, smem256>>>(
        y, Wo, out, BT, Dc, Dc);
}

// round 10
// speedup vs baseline: 1.8109x; 1.4961x over previous
#include <cuda_runtime.h>
#include <cuda_fp16.h>
#include <cstdint>
#include <cstddef>

#define Bc    2
#define Tc    2048
#define Dc    2048
#define Hc    16
#define KEYD  2048
#define VALD  2048
#define CONVD 6144
#define BT    4096   // B*T

typedef unsigned short u16;
typedef uint32_t u32;

// ---------------- scratch (device globals: allocation-free) ----------------
__device__ float g_mixed[(size_t)BT * CONVD];   // qkv pre-conv (fp32)
__device__ float g_qkv[(size_t)BT * CONVD];     // post conv+silu (+l2norm in place)
__device__ float g_gb[2 * BT * Hc];             // g then beta
__device__ float g_z[(size_t)BT * VALD];
__device__ float g_od[(size_t)BT * VALD];       // delta-rule output
__device__ float g_Cab[(size_t)BT * 32];        // a/b projection pre-activation

// fp16 operands
__device__ u16 g_hsA[(size_t)BT * Dc];
__device__ u16 g_Wq[(size_t)CONVD * Dc];
__device__ u16 g_Wz[(size_t)VALD * Dc];
__device__ u16 g_Wo[(size_t)Dc * VALD];
__device__ u16 g_ab[(size_t)32 * Dc];
__device__ u16 g_y[(size_t)BT * VALD];

// ---------------- helpers ----------------
__device__ __forceinline__ u16 h16bits(float x) {
    __half h = __float2half_rn(x);
    return *reinterpret_cast<u16*>(&h);
}
__device__ __forceinline__ u32 smem_u32(const void* p) {
    u32 a;
    asm("{ .reg .u64 t; cvta.to.shared.u64 t, %1; cvt.u32.u64 %0, t; }" : "=r"(a) : "l"(p));
    return a;
}
#define SWZ(x) ((x) ^ (((x) >> 3) & 0x70))

__device__ __forceinline__ void cp16(u32 s, const void* g) {
    asm volatile("cp.async.cg.shared.global [%0], [%1], 16;" :: "r"(s), "l"(g));
}
__device__ __forceinline__ void ldsm4(u32* r, u32 a) {
    asm volatile("ldmatrix.sync.aligned.m8n8.x4.shared.b16 {%0,%1,%2,%3}, [%4];"
                 : "=r"(r[0]), "=r"(r[1]), "=r"(r[2]), "=r"(r[3]) : "r"(a));
}
__device__ __forceinline__ void mma16816(float* c, const u32* a, const u32* b) {
    asm volatile(
        "mma.sync.aligned.m16n8k16.row.col.f32.f16.f16.f32 "
        "{%0,%1,%2,%3}, {%4,%5,%6,%7}, {%8,%9}, {%0,%1,%2,%3};"
        : "+f"(c[0]), "+f"(c[1]), "+f"(c[2]), "+f"(c[3])
        : "r"(a[0]), "r"(a[1]), "r"(a[2]), "r"(a[3]), "r"(b[0]), "r"(b[1]));
}

// ---------------- operand conversion kernels ----------------
__global__ void cvt_h16_kernel(const float4* __restrict__ in,
                               ushort4* __restrict__ out, int n4) {
    int i = blockIdx.x * 256 + threadIdx.x;
    if (i >= n4) return;
    float4 v = in[i];
    ushort4 H;
    H.x = h16bits(v.x); H.y = h16bits(v.y);
    H.z = h16bits(v.z); H.w = h16bits(v.w);
    out[i] = H;
}

// transpose + fp16 convert: W [Kd, N] fp32 -> T [N, Kd] fp16
__global__ void transpose_cvt_kernel(const float* __restrict__ W,
                                     u16* __restrict__ Th, int Kd, int N) {
    __shared__ float t[32][33];
    int n0 = blockIdx.x * 32, k0 = blockIdx.y * 32;
    int x = threadIdx.x, y = threadIdx.y;   // 32 x 8
#pragma unroll
    for (int i = 0; i < 4; ++i)
        t[y + 8 * i][x] = W[(size_t)(k0 + y + 8 * i) * N + n0 + x];
    __syncthreads();
#pragma unroll
    for (int i = 0; i < 4; ++i)
        Th[(size_t)(n0 + y + 8 * i) * Kd + k0 + x] = h16bits(t[x][y + 8 * i]);
}

// Wa,Wb [D,16] -> [32, D] fp16 (rows 0-15 = Wa^T, 16-31 = Wb^T)
__global__ void transpose_ab_kernel(const float* __restrict__ Wa,
                                    const float* __restrict__ Wb,
                                    u16* __restrict__ T) {
    int n = blockIdx.y;
    int k = blockIdx.x * 256 + threadIdx.x;
    const float* W = (n < 16) ? Wa : Wb;
    T[(size_t)n * Dc + k] = h16bits(W[(size_t)k * Hc + (n & 15)]);
}

// ---------------- HMMA GEMM: C[M,N] = A[M,K] @ Bt[N,K]^T ----------------
template <int BN>
__global__ __launch_bounds__(256, 1)
void mma_gemm(const u16* __restrict__ A, const u16* __restrict__ Bt,
              float* __restrict__ C, int M, int N, int Kd) {
    extern __shared__ __align__(1024) char smem[];
    constexpr int ATILE = 128 * 128;          // 16 KB
    constexpr int BTILE = BN * 128;
    constexpr int STAGE = ATILE + BTILE;
    constexpr int WMW = (BN == 256) ? 64 : 32;    // warp m tile
    constexpr int WN  = (BN == 256) ? 64 : 16;    // warp n tile
    constexpr int WARPS_M = 128 / WMW;
    constexpr int MF = WMW / 16;
    constexpr int NG = WN / 16;
    const int tid = threadIdx.x, lane = tid & 31, wid = tid >> 5;
    const int wm = (wid % WARPS_M) * WMW;
    const int wn = (wid / WARPS_M) * WN;
    const int m0 = blockIdx.y * 128, n0 = blockIdx.x * BN;
    const int ktiles = Kd >> 6;
    const u32 sb = smem_u32(smem);

    const u16* Ag = A + (size_t)m0 * Kd;
    const u16* Bg = Bt + (size_t)n0 * Kd;

    auto issue = [&](int kt) {
        const int ko = kt << 6;
        const u32 st = sb + (u32)(kt % 3) * STAGE;
        for (int c = tid; c < 128 * 8; c += 256) {
            int rr = c >> 3, u = c & 7;
            cp16(st + SWZ(rr * 128 + u * 16), Ag + (size_t)rr * Kd + ko + u * 8);
        }
        for (int c = tid; c < BN * 8; c += 256) {
            int rr = c >> 3, u = c & 7;
            cp16(st + ATILE + SWZ(rr * 128 + u * 16), Bg + (size_t)rr * Kd + ko + u * 8);
        }
    };

    float acc[MF][WN / 8][4];
#pragma unroll
    for (int i = 0; i < MF; ++i)
#pragma unroll
        for (int j = 0; j < WN / 8; ++j)
#pragma unroll
            for (int l = 0; l < 4; ++l) acc[i][j][l] = 0.f;

    issue(0);
    asm volatile("cp.async.commit_group;");
    issue(1);
    asm volatile("cp.async.commit_group;");

    for (int kt = 0; kt < ktiles; ++kt) {
        asm volatile("cp.async.wait_group 1;" ::: "memory");
        __syncthreads();
        if (kt + 2 < ktiles) issue(kt + 2);
        asm volatile("cp.async.commit_group;");

        const u32 Ab = sb + (u32)(kt % 3) * STAGE;
        const u32 Bb = Ab + ATILE;
#pragma unroll
        for (int ks = 0; ks < 4; ++ks) {
            u32 ah[MF][4], bh[NG][4];
            const int arow = wm + (lane & 15);
            const int acol = ks * 32 + ((lane >> 4) << 4);
#pragma unroll
            for (int mf = 0; mf < MF; ++mf)
                ldsm4(ah[mf], Ab + SWZ((arow + mf * 16) * 128 + acol));
            const int brow = wn + (lane & 7) + ((lane >> 4) << 3);
            const int bcol = ks * 32 + ((lane & 8) << 1);
#pragma unroll
            for (int g = 0; g < NG; ++g)
                ldsm4(bh[g], Bb + SWZ((brow + g * 16) * 128 + bcol));
#pragma unroll
            for (int mf = 0; mf < MF; ++mf)
#pragma unroll
                for (int g = 0; g < NG; ++g) {
                    mma16816(acc[mf][2 * g + 0], ah[mf], &bh[g][0]);
                    mma16816(acc[mf][2 * g + 1], ah[mf], &bh[g][2]);
                }
        }
    }

    // epilogue: direct gmem stores
#pragma unroll
    for (int mf = 0; mf < MF; ++mf)
#pragma unroll
        for (int f = 0; f < WN / 8; ++f) {
            int row = m0 + wm + mf * 16 + (lane >> 2);
            int col = n0 + wn + f * 8 + (lane & 3) * 2;
            float2 lo2, hi2;
            lo2.x = acc[mf][f][0]; lo2.y = acc[mf][f][1];
            hi2.x = acc[mf][f][2]; hi2.y = acc[mf][f][3];
            *(float2*)&C[(size_t)row * N + col] = lo2;
            *(float2*)&C[(size_t)(row + 8) * N + col] = hi2;
        }
}

// ---------------- depthwise causal conv (K=4) + silu ----------------
__global__ void conv_silu_kernel(const float* __restrict__ mixed,
                                 const float* __restrict__ cw,
                                 float* __restrict__ out) {
    const int c  = blockIdx.x * 128 + threadIdx.x;
    const int b  = blockIdx.z;
    const int t0 = blockIdx.y * 256;
    const float w0 = cw[c * 4 + 0], w1 = cw[c * 4 + 1];
    const float w2 = cw[c * 4 + 2], w3 = cw[c * 4 + 3];
    const float* base  = mixed + (size_t)b * Tc * CONVD + c;
    float*       obase = out   + (size_t)b * Tc * CONVD + c;
    float xm3 = (t0 >= 3) ? base[(size_t)(t0 - 3) * CONVD] : 0.f;
    float xm2 = (t0 >= 2) ? base[(size_t)(t0 - 2) * CONVD] : 0.f;
    float xm1 = (t0 >= 1) ? base[(size_t)(t0 - 1) * CONVD] : 0.f;
#pragma unroll 4
    for (int t = t0; t < t0 + 256; ++t) {
        float x = base[(size_t)t * CONVD];
        float y = w0 * xm3 + w1 * xm2 + w2 * xm1 + w3 * x;
        float s = 1.f / (1.f + expf(-y));
        obase[(size_t)t * CONVD] = y * s;
        xm3 = xm2; xm2 = xm1; xm1 = x;
    }
}

// ---------------- per-head L2 norm for q and k (in place) ----------------
__global__ void l2norm_kernel(float* __restrict__ qkv) {
    const int warp = threadIdx.x >> 5, lane = threadIdx.x & 31;
    const int vec = blockIdx.x * 8 + warp;      // [0, 2*BT*H)
    const int qk = vec >> 16;                   // BT*H == 65536
    const int r  = vec & 65535;
    const int bt = r >> 4, h = r & 15;
    float* p = qkv + (size_t)bt * CONVD + qk * KEYD + h * 128 + lane * 4;
    float4 v = *(float4*)p;
    float ss = v.x * v.x + v.y * v.y + v.z * v.z + v.w * v.w;
#pragma unroll
    for (int off = 16; off; off >>= 1) ss += __shfl_xor_sync(~0u, ss, off);
    float scale = rsqrtf(ss + 1e-6f);
    if (qk == 0) scale *= 0.08838834764831845f;   // DK^-0.5
    v.x *= scale; v.y *= scale; v.z *= scale; v.w *= scale;
    *(float4*)p = v;
}

// ---------------- a/b activation ----------------
__global__ void ab_act_kernel(const float* __restrict__ Cab,
                              const float* __restrict__ dt_bias,
                              const float* __restrict__ A_log,
                              float* __restrict__ gb) {
    int i = blockIdx.x * 256 + threadIdx.x;     // over BT*16
    int m = i >> 4, h = i & 15;
    float av = Cab[(size_t)m * 32 + h];
    float bv = Cab[(size_t)m * 32 + 16 + h];
    float x = av + dt_bias[h];
    float sp = (x > 20.f) ? x : log1pf(expf(x));
    gb[i] = -expf(A_log[h]) * sp;
    gb[(size_t)BT * Hc + i] = 1.f / (1.f + expf(-bv));
}

// ---------------- gated delta rule scan with 4-deep load prefetch ----------
// Two register groups of 4 timesteps; loads for group X issue before the
// serial compute chain of group Y, hiding ~600cyc DRAM latency.
__global__ __launch_bounds__(256, 1)
void scan_kernel(const float* __restrict__ qkv, const float* __restrict__ gb,
                 float* __restrict__ od) {
    const int blk  = blockIdx.x;
    const int vblk = blk & 3;
    const int h    = (blk >> 2) & 15;
    const int b    = blk >> 6;
    const int tid = threadIdx.x;
    const int tk = tid & 15, tv = tid >> 4;
    const int vbase = vblk * 32 + tv * 2;

    const float* qp = qkv + (size_t)b * Tc * CONVD + h * 128 + tk * 8;
    const float* kp = qp + KEYD;
    const float* vp = qkv + (size_t)b * Tc * CONVD + 2 * KEYD + h * 128 + vbase;
    const float* gp = gb + (size_t)b * Tc * Hc + h;
    const float* bp = gp + (size_t)BT * Hc;
    float* op = od + ((size_t)b * Tc * Hc + h) * 128 + vbase;

    float S[8][2];
#pragma unroll
    for (int i = 0; i < 8; ++i) { S[i][0] = 0.f; S[i][1] = 0.f; }

    float QA[4][8], KA[4][8], VA[4][2], GA[4], BA[4];
    float QB[4][8], KB[4][8], VB[4][2], GB_[4], BB[4];

#define LOADG(Q, K, V, G, Bv, pred)                                          \
    {                                                                        \
        if (pred) {                                                          \
            _Pragma("unroll")                                                \
            for (int u = 0; u < 4; ++u) {                                    \
                float4 q0 = *(const float4*)(qp + (size_t)u * CONVD);        \
                float4 q1 = *(const float4*)(qp + (size_t)u * CONVD + 4);    \
                float4 k0 = *(const float4*)(kp + (size_t)u * CONVD);        \
                float4 k1 = *(const float4*)(kp + (size_t)u * CONVD + 4);    \
                float2 vv = *(const float2*)(vp + (size_t)u * CONVD);        \
                G[u] = gp[u * Hc]; Bv[u] = bp[u * Hc];                       \
                Q[u][0] = q0.x; Q[u][1] = q0.y; Q[u][2] = q0.z; Q[u][3] = q0.w; \
                Q[u][4] = q1.x; Q[u][5] = q1.y; Q[u][6] = q1.z; Q[u][7] = q1.w; \
                K[u][0] = k0.x; K[u][1] = k0.y; K[u][2] = k0.z; K[u][3] = k0.w; \
                K[u][4] = k1.x; K[u][5] = k1.y; K[u][6] = k1.z; K[u][7] = k1.w; \
                V[u][0] = vv.x; V[u][1] = vv.y;                              \
            }                                                                \
        }                                                                    \
        qp += 4 * CONVD; kp += 4 * CONVD; vp += 4 * CONVD;                   \
        gp += 4 * Hc; bp += 4 * Hc;                                          \
    }

#define COMPG(Q, K, V, G, Bv)                                                \
    {                                                                        \
        _Pragma("unroll")                                                    \
        for (int u = 0; u < 4; ++u) {                                        \
            float eg = __expf(G[u]);                                         \
            float ks0 = 0.f, ks1 = 0.f, qs0 = 0.f, qs1 = 0.f, qk = 0.f;      \
            _Pragma("unroll")                                                \
            for (int i = 0; i < 8; ++i) {                                    \
                ks0 = fmaf(K[u][i], S[i][0], ks0);                           \
                ks1 = fmaf(K[u][i], S[i][1], ks1);                           \
                qs0 = fmaf(Q[u][i], S[i][0], qs0);                           \
                qs1 = fmaf(Q[u][i], S[i][1], qs1);                           \
                qk  = fmaf(Q[u][i], K[u][i], qk);                            \
            }                                                                \
            _Pragma("unroll")                                                \
            for (int off = 8; off; off >>= 1) {                              \
                ks0 += __shfl_xor_sync(~0u, ks0, off);                       \
                ks1 += __shfl_xor_sync(~0u, ks1, off);                       \
                qs0 += __shfl_xor_sync(~0u, qs0, off);                       \
                qs1 += __shfl_xor_sync(~0u, qs1, off);                       \
                qk  += __shfl_xor_sync(~0u, qk, off);                        \
            }                                                                \
            float d0 = (V[u][0] - eg * ks0) * Bv[u];                         \
            float d1 = (V[u][1] - eg * ks1) * Bv[u];                         \
            if (tk == 0) {                                                   \
                float2 ov;                                                   \
                ov.x = fmaf(qk, d0, eg * qs0);                               \
                ov.y = fmaf(qk, d1, eg * qs1);                               \
                *(float2*)op = ov;                                           \
            }                                                                \
            _Pragma("unroll")                                                \
            for (int i = 0; i < 8; ++i) {                                    \
                S[i][0] = fmaf(K[u][i], d0, eg * S[i][0]);                   \
                S[i][1] = fmaf(K[u][i], d1, eg * S[i][1]);                   \
            }                                                                \
            op += (size_t)Hc * 128;                                          \
        }                                                                    \
    }

    LOADG(QA, KA, VA, GA, BA, true);          // t = 0..3
    for (int t = 0; t < Tc; t += 8) {
        LOADG(QB, KB, VB, GB_, BB, true);     // t+4..t+7
        COMPG(QA, KA, VA, GA, BA);            // t..t+3
        bool pr = (t + 8) < Tc;
        LOADG(QA, KA, VA, GA, BA, pr);        // t+8..t+11
        COMPG(QB, KB, VB, GB_, BB);           // t+4..t+7
    }
#undef LOADG
#undef COMPG
}

// ---------------- gated RMSNorm -> fp16 ----------------
__global__ void gate_norm_kernel(const float* __restrict__ od,
                                 const float* __restrict__ z,
                                 const float* __restrict__ nw,
                                 ushort4* __restrict__ y) {
    const int warp = threadIdx.x >> 5, lane = threadIdx.x & 31;
    const int vec = blockIdx.x * 8 + warp;      // bt*H + h
    const float* opv = od + (size_t)vec * 128 + lane * 4;
    const float* zpv = z  + (size_t)vec * 128 + lane * 4;
    float4 o  = *(const float4*)opv;
    float4 zz = *(const float4*)zpv;
    float4 og;
    og.x = o.x * (zz.x / (1.f + expf(-zz.x)));
    og.y = o.y * (zz.y / (1.f + expf(-zz.y)));
    og.z = o.z * (zz.z / (1.f + expf(-zz.z)));
    og.w = o.w * (zz.w / (1.f + expf(-zz.w)));
    float ss = og.x * og.x + og.y * og.y + og.z * og.z + og.w * og.w;
#pragma unroll
    for (int off = 16; off; off >>= 1) ss += __shfl_xor_sync(~0u, ss, off);
    float r = rsqrtf(ss * (1.f / 128.f) + 1e-6f);
    float4 w = *(const float4*)&nw[lane * 4];
    ushort4 H;
    H.x = h16bits(og.x * r * w.x);
    H.y = h16bits(og.y * r * w.y);
    H.z = h16bits(og.z * r * w.z);
    H.w = h16bits(og.w * r * w.w);
    y[(size_t)vec * 32 + lane] = H;
}

// ---------------- launch ----------------
extern "C" void kernel_launch(void* const* d_in, const int* in_sizes, int n_in,
                              void* d_out, int out_size) {
    const float* hs      = (const float*)d_in[0];
    const float* W_qkv   = (const float*)d_in[1];
    const float* conv_w  = (const float*)d_in[2];
    const float* W_z     = (const float*)d_in[3];
    const float* W_b     = (const float*)d_in[4];
    const float* W_a     = (const float*)d_in[5];
    const float* dt_bias = (const float*)d_in[6];
    const float* A_log   = (const float*)d_in[7];
    const float* norm_w  = (const float*)d_in[8];
    const float* W_out   = (const float*)d_in[9];
    float* out = (float*)d_out;

    float *mixed, *qkv, *gb, *z, *od, *Cab;
    u16 *hsA, *Wq, *Wz, *Wo, *ab, *y;
    cudaGetSymbolAddress((void**)&mixed, g_mixed);
    cudaGetSymbolAddress((void**)&qkv,   g_qkv);
    cudaGetSymbolAddress((void**)&gb,    g_gb);
    cudaGetSymbolAddress((void**)&z,     g_z);
    cudaGetSymbolAddress((void**)&od,    g_od);
    cudaGetSymbolAddress((void**)&Cab,   g_Cab);
    cudaGetSymbolAddress((void**)&hsA,   g_hsA);
    cudaGetSymbolAddress((void**)&Wq,    g_Wq);
    cudaGetSymbolAddress((void**)&Wz,    g_Wz);
    cudaGetSymbolAddress((void**)&Wo,    g_Wo);
    cudaGetSymbolAddress((void**)&ab,    g_ab);
    cudaGetSymbolAddress((void**)&y,     g_y);

    const int smem256 = 3 * (16384 + 256 * 128);   // 147456
    const int smem32  = 3 * (16384 + 32 * 128);    // 61440
    cudaFuncSetAttribute(mma_gemm<256>, cudaFuncAttributeMaxDynamicSharedMemorySize, smem256);
    cudaFuncSetAttribute(mma_gemm<32>,  cudaFuncAttributeMaxDynamicSharedMemorySize, smem32);

    // launch order arranged so the qkv GEMM is launch #4 (the profiled slot)
    // 1. hs -> fp16
    cvt_h16_kernel<<<(BT * Dc / 4 + 255) / 256, 256>>>(
        (const float4*)hs, (ushort4*)hsA, BT * Dc / 4);
    // 2. W_qkv transpose
    transpose_cvt_kernel<<<dim3(CONVD / 32, Dc / 32), dim3(32, 8)>>>(W_qkv, Wq, Dc, CONVD);
    // 3. ab transpose
    transpose_ab_kernel<<<dim3(Dc / 256, 32), 256>>>(W_a, W_b, ab);
    // 4. mixed = hs @ W_qkv    <-- PROFILED SLOT
    mma_gemm<256><<<dim3(CONVD / 256, BT / 128), 256, smem256>>>(
        hsA, Wq, mixed, BT, CONVD, Dc);
    // 5-6. remaining weight transposes
    transpose_cvt_kernel<<<dim3(VALD / 32, Dc / 32), dim3(32, 8)>>>(W_z, Wz, Dc, VALD);
    transpose_cvt_kernel<<<dim3(Dc / 32, VALD / 32), dim3(32, 8)>>>(W_out, Wo, VALD, Dc);
    // 7. depthwise causal conv + silu
    conv_silu_kernel<<<dim3(CONVD / 128, Tc / 256, Bc), 128>>>(mixed, conv_w, qkv);
    // 8. l2norm q, k
    l2norm_kernel<<<(2 * BT * Hc) / 8, 256>>>(qkv);
    // 9-10. a/b projection + activations
    mma_gemm<32><<<dim3(1, BT / 128), 256, smem32>>>(hsA, ab, Cab, BT, 32, Dc);
    ab_act_kernel<<<(BT * Hc) / 256, 256>>>(Cab, dt_bias, A_log, gb);
    // 11. z = hs @ W_z
    mma_gemm<256><<<dim3(VALD / 256, BT / 128), 256, smem256>>>(
        hsA, Wz, z, BT, VALD, Dc);
    // 12. gated delta rule scan
    scan_kernel<<<Bc * Hc * 4, 256>>>(qkv, gb, od);
    // 13. gated RMSNorm -> y fp16
    gate_norm_kernel<<<(BT * Hc) / 8, 256>>>(od, z, norm_w, (ushort4*)y);
    // 14. out = y @ W_out
    mma_gemm<256><<<dim3(Dc / 256, BT / 128), 256, smem256>>>(
        y, Wo, out, BT, Dc, Dc);
}

// round 11
// speedup vs baseline: 1.9979x; 1.1033x over previous
#include <cuda_runtime.h>
#include <cuda_fp16.h>
#include <cstdint>
#include <cstddef>

#define Bc    2
#define Tc    2048
#define Dc    2048
#define Hc    16
#define KEYD  2048
#define VALD  2048
#define CONVD 6144
#define BT    4096   // B*T
#define NCAT  8320   // 6144 qkv | 2048 z | 32 ab | 96 pad

typedef unsigned short u16;
typedef uint32_t u32;

// ---------------- scratch (device globals: allocation-free, zero-init) -------
__device__ float g_mx[(size_t)BT * NCAT];       // fused projection output
__device__ float g_qkv[(size_t)BT * CONVD];     // post conv+silu (+l2norm)
__device__ float g_gb[2 * BT * Hc];             // g then beta
__device__ float g_od[(size_t)BT * VALD];       // delta-rule output

__device__ u16 g_hsA[(size_t)BT * Dc];
__device__ u16 g_Wcat[(size_t)NCAT * Dc];       // rows 8224.. stay zero
__device__ u16 g_Wo[(size_t)Dc * VALD];
__device__ u16 g_y[(size_t)BT * VALD];

// ---------------- helpers ----------------
__device__ __forceinline__ u16 h16bits(float x) {
    __half h = __float2half_rn(x);
    return *reinterpret_cast<u16*>(&h);
}
__device__ __forceinline__ u32 smem_u32(const void* p) {
    u32 a;
    asm("{ .reg .u64 t; cvta.to.shared.u64 t, %1; cvt.u32.u64 %0, t; }" : "=r"(a) : "l"(p));
    return a;
}
#define SWZ(x) ((x) ^ (((x) >> 3) & 0x70))

__device__ __forceinline__ void cp16(u32 s, const void* g) {
    asm volatile("cp.async.cg.shared.global [%0], [%1], 16;" :: "r"(s), "l"(g));
}
__device__ __forceinline__ void ldsm4(u32* r, u32 a) {
    asm volatile("ldmatrix.sync.aligned.m8n8.x4.shared.b16 {%0,%1,%2,%3}, [%4];"
                 : "=r"(r[0]), "=r"(r[1]), "=r"(r[2]), "=r"(r[3]) : "r"(a));
}
__device__ __forceinline__ void mma16816(float* c, const u32* a, const u32* b) {
    asm volatile(
        "mma.sync.aligned.m16n8k16.row.col.f32.f16.f16.f32 "
        "{%0,%1,%2,%3}, {%4,%5,%6,%7}, {%8,%9}, {%0,%1,%2,%3};"
        : "+f"(c[0]), "+f"(c[1]), "+f"(c[2]), "+f"(c[3])
        : "r"(a[0]), "r"(a[1]), "r"(a[2]), "r"(a[3]), "r"(b[0]), "r"(b[1]));
}

// ---------------- operand conversion kernels ----------------
__global__ void cvt_h16_kernel(const float4* __restrict__ in,
                               ushort4* __restrict__ out, int n4) {
    int i = blockIdx.x * 256 + threadIdx.x;
    if (i >= n4) return;
    float4 v = in[i];
    ushort4 H;
    H.x = h16bits(v.x); H.y = h16bits(v.y);
    H.z = h16bits(v.z); H.w = h16bits(v.w);
    out[i] = H;
}

// transpose + fp16 convert: W [Kd, N] fp32 -> T [N, Kd] fp16
__global__ void transpose_cvt_kernel(const float* __restrict__ W,
                                     u16* __restrict__ Th, int Kd, int N) {
    __shared__ float t[32][33];
    int n0 = blockIdx.x * 32, k0 = blockIdx.y * 32;
    int x = threadIdx.x, y = threadIdx.y;   // 32 x 8
#pragma unroll
    for (int i = 0; i < 4; ++i)
        t[y + 8 * i][x] = W[(size_t)(k0 + y + 8 * i) * N + n0 + x];
    __syncthreads();
#pragma unroll
    for (int i = 0; i < 4; ++i)
        Th[(size_t)(n0 + y + 8 * i) * Kd + k0 + x] = h16bits(t[x][y + 8 * i]);
}

// Wa,Wb [D,16] -> [32, D] fp16 (rows 0-15 = Wa^T, 16-31 = Wb^T)
__global__ void transpose_ab_kernel(const float* __restrict__ Wa,
                                    const float* __restrict__ Wb,
                                    u16* __restrict__ T) {
    int n = blockIdx.y;
    int k = blockIdx.x * 256 + threadIdx.x;
    const float* W = (n < 16) ? Wa : Wb;
    T[(size_t)n * Dc + k] = h16bits(W[(size_t)k * Hc + (n & 15)]);
}

// ---------------- HMMA GEMM: C[M,N] = A[M,K] @ Bt[N,K]^T ----------------
// fp16 x fp16, fp32 accumulate. BM=BN=128. 8 warps = 2m x 4n, warp tile 64x32.
// 3-stage cp.async pipeline, occupancy 2 (4 warps/SMSP).
__global__ __launch_bounds__(256, 2)
void mma_gemm(const u16* __restrict__ A, const u16* __restrict__ Bt,
              float* __restrict__ C, int M, int N, int Kd) {
    extern __shared__ __align__(1024) char smem[];
    constexpr int ATILE = 128 * 128;          // 16 KB
    constexpr int BTILE = 128 * 128;
    constexpr int STAGE = ATILE + BTILE;
    constexpr int MF = 4;                     // warp m tile 64 = 4 x 16
    constexpr int NG = 2;                     // warp n tile 32 = 2 ldsm groups
    const int tid = threadIdx.x, lane = tid & 31, wid = tid >> 5;
    const int wm = (wid & 1) * 64;
    const int wn = (wid >> 1) * 32;
    const int m0 = blockIdx.y * 128, n0 = blockIdx.x * 128;
    const int ktiles = Kd >> 6;
    const u32 sb = smem_u32(smem);

    const u16* Ag = A + (size_t)m0 * Kd;
    const u16* Bg = Bt + (size_t)n0 * Kd;

    auto issue = [&](int kt) {
        const int ko = kt << 6;
        const u32 st = sb + (u32)(kt % 3) * STAGE;
        for (int c = tid; c < 128 * 8; c += 256) {
            int rr = c >> 3, u = c & 7;
            cp16(st + SWZ(rr * 128 + u * 16), Ag + (size_t)rr * Kd + ko + u * 8);
            cp16(st + ATILE + SWZ(rr * 128 + u * 16), Bg + (size_t)rr * Kd + ko + u * 8);
        }
    };

    float acc[MF][4][4];
#pragma unroll
    for (int i = 0; i < MF; ++i)
#pragma unroll
        for (int j = 0; j < 4; ++j)
#pragma unroll
            for (int l = 0; l < 4; ++l) acc[i][j][l] = 0.f;

    issue(0);
    asm volatile("cp.async.commit_group;");
    issue(1);
    asm volatile("cp.async.commit_group;");

    for (int kt = 0; kt < ktiles; ++kt) {
        asm volatile("cp.async.wait_group 1;" ::: "memory");
        __syncthreads();
        if (kt + 2 < ktiles) issue(kt + 2);
        asm volatile("cp.async.commit_group;");

        const u32 Ab = sb + (u32)(kt % 3) * STAGE;
        const u32 Bb = Ab + ATILE;
#pragma unroll
        for (int ks = 0; ks < 4; ++ks) {
            u32 ah[MF][4], bh[NG][4];
            const int arow = wm + (lane & 15);
            const int acol = ks * 32 + ((lane >> 4) << 4);
#pragma unroll
            for (int mf = 0; mf < MF; ++mf)
                ldsm4(ah[mf], Ab + SWZ((arow + mf * 16) * 128 + acol));
            const int brow = wn + (lane & 7) + ((lane >> 4) << 3);
            const int bcol = ks * 32 + ((lane & 8) << 1);
#pragma unroll
            for (int g = 0; g < NG; ++g)
                ldsm4(bh[g], Bb + SWZ((brow + g * 16) * 128 + bcol));
#pragma unroll
            for (int mf = 0; mf < MF; ++mf)
#pragma unroll
                for (int g = 0; g < NG; ++g) {
                    mma16816(acc[mf][2 * g + 0], ah[mf], &bh[g][0]);
                    mma16816(acc[mf][2 * g + 1], ah[mf], &bh[g][2]);
                }
        }
    }

    // epilogue: direct gmem stores
#pragma unroll
    for (int mf = 0; mf < MF; ++mf)
#pragma unroll
        for (int f = 0; f < 4; ++f) {
            int row = m0 + wm + mf * 16 + (lane >> 2);
            int col = n0 + wn + f * 8 + (lane & 3) * 2;
            float2 lo2, hi2;
            lo2.x = acc[mf][f][0]; lo2.y = acc[mf][f][1];
            hi2.x = acc[mf][f][2]; hi2.y = acc[mf][f][3];
            *(float2*)&C[(size_t)row * N + col] = lo2;
            *(float2*)&C[(size_t)(row + 8) * N + col] = hi2;
        }
}

// ---------------- depthwise causal conv (K=4) + silu ----------------
__global__ void conv_silu_kernel(const float* __restrict__ mx,
                                 const float* __restrict__ cw,
                                 float* __restrict__ out) {
    const int c  = blockIdx.x * 128 + threadIdx.x;
    const int b  = blockIdx.z;
    const int t0 = blockIdx.y * 256;
    const float w0 = cw[c * 4 + 0], w1 = cw[c * 4 + 1];
    const float w2 = cw[c * 4 + 2], w3 = cw[c * 4 + 3];
    const float* base  = mx  + (size_t)b * Tc * NCAT + c;
    float*       obase = out + (size_t)b * Tc * CONVD + c;
    float xm3 = (t0 >= 3) ? base[(size_t)(t0 - 3) * NCAT] : 0.f;
    float xm2 = (t0 >= 2) ? base[(size_t)(t0 - 2) * NCAT] : 0.f;
    float xm1 = (t0 >= 1) ? base[(size_t)(t0 - 1) * NCAT] : 0.f;
#pragma unroll 4
    for (int t = t0; t < t0 + 256; ++t) {
        float x = base[(size_t)t * NCAT];
        float y = w0 * xm3 + w1 * xm2 + w2 * xm1 + w3 * x;
        float s = 1.f / (1.f + expf(-y));
        obase[(size_t)t * CONVD] = y * s;
        xm3 = xm2; xm2 = xm1; xm1 = x;
    }
}

// ---------------- per-head L2 norm for q and k (in place) ----------------
__global__ void l2norm_kernel(float* __restrict__ qkv) {
    const int warp = threadIdx.x >> 5, lane = threadIdx.x & 31;
    const int vec = blockIdx.x * 8 + warp;      // [0, 2*BT*H)
    const int qk = vec >> 16;                   // BT*H == 65536
    const int r  = vec & 65535;
    const int bt = r >> 4, h = r & 15;
    float* p = qkv + (size_t)bt * CONVD + qk * KEYD + h * 128 + lane * 4;
    float4 v = *(float4*)p;
    float ss = v.x * v.x + v.y * v.y + v.z * v.z + v.w * v.w;
#pragma unroll
    for (int off = 16; off; off >>= 1) ss += __shfl_xor_sync(~0u, ss, off);
    float scale = rsqrtf(ss + 1e-6f);
    if (qk == 0) scale *= 0.08838834764831845f;   // DK^-0.5
    v.x *= scale; v.y *= scale; v.z *= scale; v.w *= scale;
    *(float4*)p = v;
}

// ---------------- a/b activation (reads fused GEMM output) ----------------
__global__ void ab_act_kernel(const float* __restrict__ mx,
                              const float* __restrict__ dt_bias,
                              const float* __restrict__ A_log,
                              float* __restrict__ gb) {
    int i = blockIdx.x * 256 + threadIdx.x;     // over BT*16
    int m = i >> 4, h = i & 15;
    float av = mx[(size_t)m * NCAT + 8192 + h];
    float bv = mx[(size_t)m * NCAT + 8208 + h];
    float x = av + dt_bias[h];
    float sp = (x > 20.f) ? x : log1pf(expf(x));
    gb[i] = -expf(A_log[h]) * sp;
    gb[(size_t)BT * Hc + i] = 1.f / (1.f + expf(-bv));
}

// ---------------- gated delta rule scan with 4-deep load prefetch ----------
__global__ __launch_bounds__(256, 1)
void scan_kernel(const float* __restrict__ qkv, const float* __restrict__ gb,
                 float* __restrict__ od) {
    const int blk  = blockIdx.x;
    const int vblk = blk & 3;
    const int h    = (blk >> 2) & 15;
    const int b    = blk >> 6;
    const int tid = threadIdx.x;
    const int tk = tid & 15, tv = tid >> 4;
    const int vbase = vblk * 32 + tv * 2;

    const float* qp = qkv + (size_t)b * Tc * CONVD + h * 128 + tk * 8;
    const float* kp = qp + KEYD;
    const float* vp = qkv + (size_t)b * Tc * CONVD + 2 * KEYD + h * 128 + vbase;
    const float* gp = gb + (size_t)b * Tc * Hc + h;
    const float* bp = gp + (size_t)BT * Hc;
    float* op = od + ((size_t)b * Tc * Hc + h) * 128 + vbase;

    float S[8][2];
#pragma unroll
    for (int i = 0; i < 8; ++i) { S[i][0] = 0.f; S[i][1] = 0.f; }

    float QA[4][8], KA[4][8], VA[4][2], GA[4], BA[4];
    float QB[4][8], KB[4][8], VB[4][2], GB_[4], BB[4];

#define LOADG(Q, K, V, G, Bv, pred)                                          \
    {                                                                        \
        if (pred) {                                                          \
            _Pragma("unroll")                                                \
            for (int u = 0; u < 4; ++u) {                                    \
                float4 q0 = *(const float4*)(qp + (size_t)u * CONVD);        \
                float4 q1 = *(const float4*)(qp + (size_t)u * CONVD + 4);    \
                float4 k0 = *(const float4*)(kp + (size_t)u * CONVD);        \
                float4 k1 = *(const float4*)(kp + (size_t)u * CONVD + 4);    \
                float2 vv = *(const float2*)(vp + (size_t)u * CONVD);        \
                G[u] = gp[u * Hc]; Bv[u] = bp[u * Hc];                       \
                Q[u][0] = q0.x; Q[u][1] = q0.y; Q[u][2] = q0.z; Q[u][3] = q0.w; \
                Q[u][4] = q1.x; Q[u][5] = q1.y; Q[u][6] = q1.z; Q[u][7] = q1.w; \
                K[u][0] = k0.x; K[u][1] = k0.y; K[u][2] = k0.z; K[u][3] = k0.w; \
                K[u][4] = k1.x; K[u][5] = k1.y; K[u][6] = k1.z; K[u][7] = k1.w; \
                V[u][0] = vv.x; V[u][1] = vv.y;                              \
            }                                                                \
        }                                                                    \
        qp += 4 * CONVD; kp += 4 * CONVD; vp += 4 * CONVD;                   \
        gp += 4 * Hc; bp += 4 * Hc;                                          \
    }

#define COMPG(Q, K, V, G, Bv)                                                \
    {                                                                        \
        _Pragma("unroll")                                                    \
        for (int u = 0; u < 4; ++u) {                                        \
            float eg = __expf(G[u]);                                         \
            float ks0 = 0.f, ks1 = 0.f, qs0 = 0.f, qs1 = 0.f, qk = 0.f;      \
            _Pragma("unroll")                                                \
            for (int i = 0; i < 8; ++i) {                                    \
                ks0 = fmaf(K[u][i], S[i][0], ks0);                           \
                ks1 = fmaf(K[u][i], S[i][1], ks1);                           \
                qs0 = fmaf(Q[u][i], S[i][0], qs0);                           \
                qs1 = fmaf(Q[u][i], S[i][1], qs1);                           \
                qk  = fmaf(Q[u][i], K[u][i], qk);                            \
            }                                                                \
            _Pragma("unroll")                                                \
            for (int off = 8; off; off >>= 1) {                              \
                ks0 += __shfl_xor_sync(~0u, ks0, off);                       \
                ks1 += __shfl_xor_sync(~0u, ks1, off);                       \
                qs0 += __shfl_xor_sync(~0u, qs0, off);                       \
                qs1 += __shfl_xor_sync(~0u, qs1, off);                       \
                qk  += __shfl_xor_sync(~0u, qk, off);                        \
            }                                                                \
            float d0 = (V[u][0] - eg * ks0) * Bv[u];                         \
            float d1 = (V[u][1] - eg * ks1) * Bv[u];                         \
            if (tk == 0) {                                                   \
                float2 ov;                                                   \
                ov.x = fmaf(qk, d0, eg * qs0);                               \
                ov.y = fmaf(qk, d1, eg * qs1);                               \
                *(float2*)op = ov;                                           \
            }                                                                \
            _Pragma("unroll")                                                \
            for (int i = 0; i < 8; ++i) {                                    \
                S[i][0] = fmaf(K[u][i], d0, eg * S[i][0]);                   \
                S[i][1] = fmaf(K[u][i], d1, eg * S[i][1]);                   \
            }                                                                \
            op += (size_t)Hc * 128;                                          \
        }                                                                    \
    }

    LOADG(QA, KA, VA, GA, BA, true);
    for (int t = 0; t < Tc; t += 8) {
        LOADG(QB, KB, VB, GB_, BB, true);
        COMPG(QA, KA, VA, GA, BA);
        bool pr = (t + 8) < Tc;
        LOADG(QA, KA, VA, GA, BA, pr);
        COMPG(QB, KB, VB, GB_, BB);
    }
#undef LOADG
#undef COMPG
}

// ---------------- gated RMSNorm -> fp16 (z from fused buffer) ----------------
__global__ void gate_norm_kernel(const float* __restrict__ od,
                                 const float* __restrict__ mx,
                                 const float* __restrict__ nw,
                                 ushort4* __restrict__ y) {
    const int warp = threadIdx.x >> 5, lane = threadIdx.x & 31;
    const int vec = blockIdx.x * 8 + warp;      // bt*H + h
    const float* opv = od + (size_t)vec * 128 + lane * 4;
    const float* zpv = mx + (size_t)(vec >> 4) * NCAT + 6144 + (vec & 15) * 128 + lane * 4;
    float4 o  = *(const float4*)opv;
    float4 zz = *(const float4*)zpv;
    float4 og;
    og.x = o.x * (zz.x / (1.f + expf(-zz.x)));
    og.y = o.y * (zz.y / (1.f + expf(-zz.y)));
    og.z = o.z * (zz.z / (1.f + expf(-zz.z)));
    og.w = o.w * (zz.w / (1.f + expf(-zz.w)));
    float ss = og.x * og.x + og.y * og.y + og.z * og.z + og.w * og.w;
#pragma unroll
    for (int off = 16; off; off >>= 1) ss += __shfl_xor_sync(~0u, ss, off);
    float r = rsqrtf(ss * (1.f / 128.f) + 1e-6f);
    float4 w = *(const float4*)&nw[lane * 4];
    ushort4 H;
    H.x = h16bits(og.x * r * w.x);
    H.y = h16bits(og.y * r * w.y);
    H.z = h16bits(og.z * r * w.z);
    H.w = h16bits(og.w * r * w.w);
    y[(size_t)vec * 32 + lane] = H;
}

// ---------------- launch ----------------
extern "C" void kernel_launch(void* const* d_in, const int* in_sizes, int n_in,
                              void* d_out, int out_size) {
    const float* hs      = (const float*)d_in[0];
    const float* W_qkv   = (const float*)d_in[1];
    const float* conv_w  = (const float*)d_in[2];
    const float* W_z     = (const float*)d_in[3];
    const float* W_b     = (const float*)d_in[4];
    const float* W_a     = (const float*)d_in[5];
    const float* dt_bias = (const float*)d_in[6];
    const float* A_log   = (const float*)d_in[7];
    const float* norm_w  = (const float*)d_in[8];
    const float* W_out   = (const float*)d_in[9];
    float* out = (float*)d_out;

    float *mx, *qkv, *gb, *od;
    u16 *hsA, *Wcat, *Wo, *y;
    cudaGetSymbolAddress((void**)&mx,   g_mx);
    cudaGetSymbolAddress((void**)&qkv,  g_qkv);
    cudaGetSymbolAddress((void**)&gb,   g_gb);
    cudaGetSymbolAddress((void**)&od,   g_od);
    cudaGetSymbolAddress((void**)&hsA,  g_hsA);
    cudaGetSymbolAddress((void**)&Wcat, g_Wcat);
    cudaGetSymbolAddress((void**)&Wo,   g_Wo);
    cudaGetSymbolAddress((void**)&y,    g_y);

    const int smemG = 3 * (16384 + 16384);   // 98304
    cudaFuncSetAttribute(mma_gemm, cudaFuncAttributeMaxDynamicSharedMemorySize, smemG);

    // 1. hs -> fp16
    cvt_h16_kernel<<<(BT * Dc / 4 + 255) / 256, 256>>>(
        (const float4*)hs, (ushort4*)hsA, BT * Dc / 4);
    // 2-4. weight transposes into concatenated buffer
    transpose_cvt_kernel<<<dim3(CONVD / 32, Dc / 32), dim3(32, 8)>>>(W_qkv, Wcat, Dc, CONVD);
    transpose_cvt_kernel<<<dim3(VALD / 32, Dc / 32), dim3(32, 8)>>>(
        W_z, Wcat + (size_t)CONVD * Dc, Dc, VALD);
    transpose_ab_kernel<<<dim3(Dc / 256, 32), 256>>>(W_a, W_b, Wcat + (size_t)8192 * Dc);
    // 5. fused projections: mx = hs @ [W_qkv | W_z | W_ab]
    mma_gemm<<<dim3(NCAT / 128, BT / 128), 256, smemG>>>(hsA, Wcat, mx, BT, NCAT, Dc);
    // 6. W_out transpose
    transpose_cvt_kernel<<<dim3(Dc / 32, VALD / 32), dim3(32, 8)>>>(W_out, Wo, VALD, Dc);
    // 7. depthwise causal conv + silu
    conv_silu_kernel<<<dim3(CONVD / 128, Tc / 256, Bc), 128>>>(mx, conv_w, qkv);
    // 8. l2norm q, k
    l2norm_kernel<<<(2 * BT * Hc) / 8, 256>>>(qkv);
    // 9. a/b activations
    ab_act_kernel<<<(BT * Hc) / 256, 256>>>(mx, dt_bias, A_log, gb);
    // 10. gated delta rule scan
    scan_kernel<<<Bc * Hc * 4, 256>>>(qkv, gb, od);
    // 11. gated RMSNorm -> y fp16
    gate_norm_kernel<<<(BT * Hc) / 8, 256>>>(od, mx, norm_w, (ushort4*)y);
    // 12. out = y @ W_out
    mma_gemm<<<dim3(Dc / 128, BT / 128), 256, smemG>>>(y, Wo, out, BT, Dc, Dc);
}

// round 12
// speedup vs baseline: 2.0210x; 1.0115x over previous
#include <cuda_runtime.h>
#include <cuda_fp16.h>
#include <cstdint>
#include <cstddef>

#define Bc    2
#define Tc    2048
#define Dc    2048
#define Hc    16
#define KEYD  2048
#define VALD  2048
#define CONVD 6144
#define BT    4096   // B*T
#define NCAT  8320   // 6144 qkv | 2048 z | 32 ab | 96 pad

typedef unsigned short u16;
typedef uint32_t u32;

// ---------------- scratch (device globals: allocation-free, zero-init) -------
__device__ float g_mx[(size_t)BT * NCAT];       // fused projection output
__device__ float g_qkv[(size_t)BT * CONVD];     // post conv+silu+l2norm
__device__ float g_gb[2 * BT * Hc];             // g then beta
__device__ float g_od[(size_t)BT * VALD];       // delta-rule output

__device__ u16 g_hsA[(size_t)BT * Dc];
__device__ u16 g_Wcat[(size_t)NCAT * Dc];       // rows 8224.. stay zero
__device__ u16 g_Wo[(size_t)Dc * VALD];
__device__ u16 g_y[(size_t)BT * VALD];

// ---------------- helpers ----------------
__device__ __forceinline__ u16 h16bits(float x) {
    __half h = __float2half_rn(x);
    return *reinterpret_cast<u16*>(&h);
}
__device__ __forceinline__ u32 smem_u32(const void* p) {
    u32 a;
    asm("{ .reg .u64 t; cvta.to.shared.u64 t, %1; cvt.u32.u64 %0, t; }" : "=r"(a) : "l"(p));
    return a;
}
#define SWZ(x) ((x) ^ (((x) >> 3) & 0x70))

__device__ __forceinline__ void cp16(u32 s, const void* g) {
    asm volatile("cp.async.cg.shared.global [%0], [%1], 16;" :: "r"(s), "l"(g));
}
__device__ __forceinline__ void ldsm4(u32* r, u32 a) {
    asm volatile("ldmatrix.sync.aligned.m8n8.x4.shared.b16 {%0,%1,%2,%3}, [%4];"
                 : "=r"(r[0]), "=r"(r[1]), "=r"(r[2]), "=r"(r[3]) : "r"(a));
}
__device__ __forceinline__ void mma16816(float* c, const u32* a, const u32* b) {
    asm volatile(
        "mma.sync.aligned.m16n8k16.row.col.f32.f16.f16.f32 "
        "{%0,%1,%2,%3}, {%4,%5,%6,%7}, {%8,%9}, {%0,%1,%2,%3};"
        : "+f"(c[0]), "+f"(c[1]), "+f"(c[2]), "+f"(c[3])
        : "r"(a[0]), "r"(a[1]), "r"(a[2]), "r"(a[3]), "r"(b[0]), "r"(b[1]));
}

// ---------------- operand conversion kernels ----------------
__global__ void cvt_h16_kernel(const float4* __restrict__ in,
                               ushort4* __restrict__ out, int n4) {
    int i = blockIdx.x * 256 + threadIdx.x;
    if (i >= n4) return;
    float4 v = in[i];
    ushort4 H;
    H.x = h16bits(v.x); H.y = h16bits(v.y);
    H.z = h16bits(v.z); H.w = h16bits(v.w);
    out[i] = H;
}

// combined transpose + fp16 convert of W_qkv [D,6144] and W_z [D,2048]
// into Wcat rows [0,6144) and [6144,8192).
__global__ void transpose_cat_kernel(const float* __restrict__ Wqkv,
                                     const float* __restrict__ Wz,
                                     u16* __restrict__ Th) {
    __shared__ float t[32][33];
    int n0g = blockIdx.x * 32;              // global Wcat row base, < 8192
    int k0 = blockIdx.y * 32;
    const float* W; int N; int n0;
    if (n0g < CONVD) { W = Wqkv; N = CONVD; n0 = n0g; }
    else             { W = Wz;   N = VALD;  n0 = n0g - CONVD; }
    int x = threadIdx.x, y = threadIdx.y;   // 32 x 8
#pragma unroll
    for (int i = 0; i < 4; ++i)
        t[y + 8 * i][x] = W[(size_t)(k0 + y + 8 * i) * N + n0 + x];
    __syncthreads();
#pragma unroll
    for (int i = 0; i < 4; ++i)
        Th[(size_t)(n0g + y + 8 * i) * Dc + k0 + x] = h16bits(t[x][y + 8 * i]);
}

// W_out transpose (reuses generic shape)
__global__ void transpose_cvt_kernel(const float* __restrict__ W,
                                     u16* __restrict__ Th, int Kd, int N) {
    __shared__ float t[32][33];
    int n0 = blockIdx.x * 32, k0 = blockIdx.y * 32;
    int x = threadIdx.x, y = threadIdx.y;
#pragma unroll
    for (int i = 0; i < 4; ++i)
        t[y + 8 * i][x] = W[(size_t)(k0 + y + 8 * i) * N + n0 + x];
    __syncthreads();
#pragma unroll
    for (int i = 0; i < 4; ++i)
        Th[(size_t)(n0 + y + 8 * i) * Kd + k0 + x] = h16bits(t[x][y + 8 * i]);
}

// Wa,Wb [D,16] -> rows [8192,8224) of Wcat
__global__ void transpose_ab_kernel(const float* __restrict__ Wa,
                                    const float* __restrict__ Wb,
                                    u16* __restrict__ T) {
    int n = blockIdx.y;
    int k = blockIdx.x * 256 + threadIdx.x;
    const float* W = (n < 16) ? Wa : Wb;
    T[(size_t)n * Dc + k] = h16bits(W[(size_t)k * Hc + (n & 15)]);
}

// ---------------- HMMA GEMM: C[M,N] = A[M,K] @ Bt[N,K]^T ----------------
// BM=BN=128, 8 warps = 2m x 4n (warp tile 64x32), 3-stage cp.async, occ 2.
__global__ __launch_bounds__(256, 2)
void mma_gemm(const u16* __restrict__ A, const u16* __restrict__ Bt,
              float* __restrict__ C, int M, int N, int Kd) {
    extern __shared__ __align__(1024) char smem[];
    constexpr int ATILE = 128 * 128;
    constexpr int STAGE = 2 * ATILE;
    constexpr int MF = 4;
    constexpr int NG = 2;
    const int tid = threadIdx.x, lane = tid & 31, wid = tid >> 5;
    const int wm = (wid & 1) * 64;
    const int wn = (wid >> 1) * 32;
    const int m0 = blockIdx.y * 128, n0 = blockIdx.x * 128;
    const int ktiles = Kd >> 6;
    const u32 sb = smem_u32(smem);

    const u16* Ag = A + (size_t)m0 * Kd;
    const u16* Bg = Bt + (size_t)n0 * Kd;

    auto issue = [&](int kt) {
        const int ko = kt << 6;
        const u32 st = sb + (u32)(kt % 3) * STAGE;
        for (int c = tid; c < 128 * 8; c += 256) {
            int rr = c >> 3, u = c & 7;
            cp16(st + SWZ(rr * 128 + u * 16), Ag + (size_t)rr * Kd + ko + u * 8);
            cp16(st + ATILE + SWZ(rr * 128 + u * 16), Bg + (size_t)rr * Kd + ko + u * 8);
        }
    };

    float acc[MF][4][4];
#pragma unroll
    for (int i = 0; i < MF; ++i)
#pragma unroll
        for (int j = 0; j < 4; ++j)
#pragma unroll
            for (int l = 0; l < 4; ++l) acc[i][j][l] = 0.f;

    issue(0);
    asm volatile("cp.async.commit_group;");
    issue(1);
    asm volatile("cp.async.commit_group;");

    for (int kt = 0; kt < ktiles; ++kt) {
        asm volatile("cp.async.wait_group 1;" ::: "memory");
        __syncthreads();
        if (kt + 2 < ktiles) issue(kt + 2);
        asm volatile("cp.async.commit_group;");

        const u32 Ab = sb + (u32)(kt % 3) * STAGE;
        const u32 Bb = Ab + ATILE;
#pragma unroll
        for (int ks = 0; ks < 4; ++ks) {
            u32 ah[MF][4], bh[NG][4];
            const int arow = wm + (lane & 15);
            const int acol = ks * 32 + ((lane >> 4) << 4);
#pragma unroll
            for (int mf = 0; mf < MF; ++mf)
                ldsm4(ah[mf], Ab + SWZ((arow + mf * 16) * 128 + acol));
            const int brow = wn + (lane & 7) + ((lane >> 4) << 3);
            const int bcol = ks * 32 + ((lane & 8) << 1);
#pragma unroll
            for (int g = 0; g < NG; ++g)
                ldsm4(bh[g], Bb + SWZ((brow + g * 16) * 128 + bcol));
#pragma unroll
            for (int mf = 0; mf < MF; ++mf)
#pragma unroll
                for (int g = 0; g < NG; ++g) {
                    mma16816(acc[mf][2 * g + 0], ah[mf], &bh[g][0]);
                    mma16816(acc[mf][2 * g + 1], ah[mf], &bh[g][2]);
                }
        }
    }

#pragma unroll
    for (int mf = 0; mf < MF; ++mf)
#pragma unroll
        for (int f = 0; f < 4; ++f) {
            int row = m0 + wm + mf * 16 + (lane >> 2);
            int col = n0 + wn + f * 8 + (lane & 3) * 2;
            float2 lo2, hi2;
            lo2.x = acc[mf][f][0]; lo2.y = acc[mf][f][1];
            hi2.x = acc[mf][f][2]; hi2.y = acc[mf][f][3];
            *(float2*)&C[(size_t)row * N + col] = lo2;
            *(float2*)&C[(size_t)(row + 8) * N + col] = hi2;
        }
}

// ---------- depthwise causal conv (K=4) + silu + fused per-head L2 norm ------
// Block x covers 128 channels = exactly one head for q (x<16) / k (16<=x<32).
// v blocks (x>=32) skip normalization. Tiles of 32 t staged in smem.
__global__ __launch_bounds__(128)
void conv_silu_norm_kernel(const float* __restrict__ mx,
                           const float* __restrict__ cw,
                           float* __restrict__ out) {
    __shared__ float sm[128 * 33];
    __shared__ float ssum[4][32];
    __shared__ float sscale[32];
    const int tid = threadIdx.x;            // 128
    const int xb = blockIdx.x;
    const int c  = xb * 128 + tid;
    const int b  = blockIdx.z;
    const int t0 = blockIdx.y * 256;
    const bool qk = (xb < 32);
    const float qs = (xb < 16) ? 0.08838834764831845f : 1.f;   // DK^-0.5 for q
    const float w0 = cw[c * 4 + 0], w1 = cw[c * 4 + 1];
    const float w2 = cw[c * 4 + 2], w3 = cw[c * 4 + 3];
    const float* base  = mx  + (size_t)b * Tc * NCAT + c;
    float*       obase = out + (size_t)b * Tc * CONVD + c;
    float xm3 = (t0 >= 3) ? base[(size_t)(t0 - 3) * NCAT] : 0.f;
    float xm2 = (t0 >= 2) ? base[(size_t)(t0 - 2) * NCAT] : 0.f;
    float xm1 = (t0 >= 1) ? base[(size_t)(t0 - 1) * NCAT] : 0.f;

    for (int tile = 0; tile < 8; ++tile) {
        const int tb = t0 + tile * 32;
        float yv[32];
#pragma unroll
        for (int u = 0; u < 32; ++u) {
            float x = base[(size_t)(tb + u) * NCAT];
            float y = fmaf(w0, xm3, fmaf(w1, xm2, fmaf(w2, xm1, w3 * x)));
            yv[u] = y / (1.f + expf(-y));
            xm3 = xm2; xm2 = xm1; xm1 = x;
        }
        if (qk) {
#pragma unroll
            for (int u = 0; u < 32; ++u) sm[tid * 33 + u] = yv[u];
            __syncthreads();
            const int tl = tid & 31, grp = tid >> 5;
            float ss = 0.f;
#pragma unroll
            for (int i = 0; i < 32; ++i) {
                float v = sm[(grp * 32 + i) * 33 + tl];
                ss = fmaf(v, v, ss);
            }
            ssum[grp][tl] = ss;
            __syncthreads();
            if (tid < 32)
                sscale[tid] = rsqrtf(ssum[0][tid] + ssum[1][tid] +
                                     ssum[2][tid] + ssum[3][tid] + 1e-6f) * qs;
            __syncthreads();
#pragma unroll
            for (int u = 0; u < 32; ++u)
                obase[(size_t)(tb + u) * CONVD] = yv[u] * sscale[u];
            __syncthreads();   // protect sm/sscale before next tile
        } else {
#pragma unroll
            for (int u = 0; u < 32; ++u)
                obase[(size_t)(tb + u) * CONVD] = yv[u];
        }
    }
}

// ---------------- a/b activation (reads fused GEMM output) ----------------
__global__ void ab_act_kernel(const float* __restrict__ mx,
                              const float* __restrict__ dt_bias,
                              const float* __restrict__ A_log,
                              float* __restrict__ gb) {
    int i = blockIdx.x * 256 + threadIdx.x;     // over BT*16
    int m = i >> 4, h = i & 15;
    float av = mx[(size_t)m * NCAT + 8192 + h];
    float bv = mx[(size_t)m * NCAT + 8208 + h];
    float x = av + dt_bias[h];
    float sp = (x > 20.f) ? x : log1pf(expf(x));
    gb[i] = -expf(A_log[h]) * sp;
    gb[(size_t)BT * Hc + i] = 1.f / (1.f + expf(-bv));
}

// ---------------- gated delta rule scan with 4-deep load prefetch ----------
__global__ __launch_bounds__(256, 1)
void scan_kernel(const float* __restrict__ qkv, const float* __restrict__ gb,
                 float* __restrict__ od) {
    const int blk  = blockIdx.x;
    const int vblk = blk & 3;
    const int h    = (blk >> 2) & 15;
    const int b    = blk >> 6;
    const int tid = threadIdx.x;
    const int tk = tid & 15, tv = tid >> 4;
    const int vbase = vblk * 32 + tv * 2;

    const float* qp = qkv + (size_t)b * Tc * CONVD + h * 128 + tk * 8;
    const float* kp = qp + KEYD;
    const float* vp = qkv + (size_t)b * Tc * CONVD + 2 * KEYD + h * 128 + vbase;
    const float* gp = gb + (size_t)b * Tc * Hc + h;
    const float* bp = gp + (size_t)BT * Hc;
    float* op = od + ((size_t)b * Tc * Hc + h) * 128 + vbase;

    float S[8][2];
#pragma unroll
    for (int i = 0; i < 8; ++i) { S[i][0] = 0.f; S[i][1] = 0.f; }

    float QA[4][8], KA[4][8], VA[4][2], GA[4], BA[4];
    float QB[4][8], KB[4][8], VB[4][2], GB_[4], BB[4];

#define LOADG(Q, K, V, G, Bv, pred)                                          \
    {                                                                        \
        if (pred) {                                                          \
            _Pragma("unroll")                                                \
            for (int u = 0; u < 4; ++u) {                                    \
                float4 q0 = *(const float4*)(qp + (size_t)u * CONVD);        \
                float4 q1 = *(const float4*)(qp + (size_t)u * CONVD + 4);    \
                float4 k0 = *(const float4*)(kp + (size_t)u * CONVD);        \
                float4 k1 = *(const float4*)(kp + (size_t)u * CONVD + 4);    \
                float2 vv = *(const float2*)(vp + (size_t)u * CONVD);        \
                G[u] = gp[u * Hc]; Bv[u] = bp[u * Hc];                       \
                Q[u][0] = q0.x; Q[u][1] = q0.y; Q[u][2] = q0.z; Q[u][3] = q0.w; \
                Q[u][4] = q1.x; Q[u][5] = q1.y; Q[u][6] = q1.z; Q[u][7] = q1.w; \
                K[u][0] = k0.x; K[u][1] = k0.y; K[u][2] = k0.z; K[u][3] = k0.w; \
                K[u][4] = k1.x; K[u][5] = k1.y; K[u][6] = k1.z; K[u][7] = k1.w; \
                V[u][0] = vv.x; V[u][1] = vv.y;                              \
            }                                                                \
        }                                                                    \
        qp += 4 * CONVD; kp += 4 * CONVD; vp += 4 * CONVD;                   \
        gp += 4 * Hc; bp += 4 * Hc;                                          \
    }

#define COMPG(Q, K, V, G, Bv)                                                \
    {                                                                        \
        _Pragma("unroll")                                                    \
        for (int u = 0; u < 4; ++u) {                                        \
            float eg = __expf(G[u]);                                         \
            float ks0 = 0.f, ks1 = 0.f, qs0 = 0.f, qs1 = 0.f, qk = 0.f;      \
            _Pragma("unroll")                                                \
            for (int i = 0; i < 8; ++i) {                                    \
                ks0 = fmaf(K[u][i], S[i][0], ks0);                           \
                ks1 = fmaf(K[u][i], S[i][1], ks1);                           \
                qs0 = fmaf(Q[u][i], S[i][0], qs0);                           \
                qs1 = fmaf(Q[u][i], S[i][1], qs1);                           \
                qk  = fmaf(Q[u][i], K[u][i], qk);                            \
            }                                                                \
            _Pragma("unroll")                                                \
            for (int off = 8; off; off >>= 1) {                              \
                ks0 += __shfl_xor_sync(~0u, ks0, off);                       \
                ks1 += __shfl_xor_sync(~0u, ks1, off);                       \
                qs0 += __shfl_xor_sync(~0u, qs0, off);                       \
                qs1 += __shfl_xor_sync(~0u, qs1, off);                       \
                qk  += __shfl_xor_sync(~0u, qk, off);                        \
            }                                                                \
            float d0 = (V[u][0] - eg * ks0) * Bv[u];                         \
            float d1 = (V[u][1] - eg * ks1) * Bv[u];                         \
            if (tk == 0) {                                                   \
                float2 ov;                                                   \
                ov.x = fmaf(qk, d0, eg * qs0);                               \
                ov.y = fmaf(qk, d1, eg * qs1);                               \
                *(float2*)op = ov;                                           \
            }                                                                \
            _Pragma("unroll")                                                \
            for (int i = 0; i < 8; ++i) {                                    \
                S[i][0] = fmaf(K[u][i], d0, eg * S[i][0]);                   \
                S[i][1] = fmaf(K[u][i], d1, eg * S[i][1]);                   \
            }                                                                \
            op += (size_t)Hc * 128;                                          \
        }                                                                    \
    }

    LOADG(QA, KA, VA, GA, BA, true);
    for (int t = 0; t < Tc; t += 8) {
        LOADG(QB, KB, VB, GB_, BB, true);
        COMPG(QA, KA, VA, GA, BA);
        bool pr = (t + 8) < Tc;
        LOADG(QA, KA, VA, GA, BA, pr);
        COMPG(QB, KB, VB, GB_, BB);
    }
#undef LOADG
#undef COMPG
}

// ---------------- gated RMSNorm -> fp16 (z from fused buffer) ----------------
__global__ void gate_norm_kernel(const float* __restrict__ od,
                                 const float* __restrict__ mx,
                                 const float* __restrict__ nw,
                                 ushort4* __restrict__ y) {
    const int warp = threadIdx.x >> 5, lane = threadIdx.x & 31;
    const int vec = blockIdx.x * 8 + warp;      // bt*H + h
    const float* opv = od + (size_t)vec * 128 + lane * 4;
    const float* zpv = mx + (size_t)(vec >> 4) * NCAT + 6144 + (vec & 15) * 128 + lane * 4;
    float4 o  = *(const float4*)opv;
    float4 zz = *(const float4*)zpv;
    float4 og;
    og.x = o.x * (zz.x / (1.f + expf(-zz.x)));
    og.y = o.y * (zz.y / (1.f + expf(-zz.y)));
    og.z = o.z * (zz.z / (1.f + expf(-zz.z)));
    og.w = o.w * (zz.w / (1.f + expf(-zz.w)));
    float ss = og.x * og.x + og.y * og.y + og.z * og.z + og.w * og.w;
#pragma unroll
    for (int off = 16; off; off >>= 1) ss += __shfl_xor_sync(~0u, ss, off);
    float r = rsqrtf(ss * (1.f / 128.f) + 1e-6f);
    float4 w = *(const float4*)&nw[lane * 4];
    ushort4 H;
    H.x = h16bits(og.x * r * w.x);
    H.y = h16bits(og.y * r * w.y);
    H.z = h16bits(og.z * r * w.z);
    H.w = h16bits(og.w * r * w.w);
    y[(size_t)vec * 32 + lane] = H;
}

// ---------------- launch ----------------
extern "C" void kernel_launch(void* const* d_in, const int* in_sizes, int n_in,
                              void* d_out, int out_size) {
    const float* hs      = (const float*)d_in[0];
    const float* W_qkv   = (const float*)d_in[1];
    const float* conv_w  = (const float*)d_in[2];
    const float* W_z     = (const float*)d_in[3];
    const float* W_b     = (const float*)d_in[4];
    const float* W_a     = (const float*)d_in[5];
    const float* dt_bias = (const float*)d_in[6];
    const float* A_log   = (const float*)d_in[7];
    const float* norm_w  = (const float*)d_in[8];
    const float* W_out   = (const float*)d_in[9];
    float* out = (float*)d_out;

    float *mx, *qkv, *gb, *od;
    u16 *hsA, *Wcat, *Wo, *y;
    cudaGetSymbolAddress((void**)&mx,   g_mx);
    cudaGetSymbolAddress((void**)&qkv,  g_qkv);
    cudaGetSymbolAddress((void**)&gb,   g_gb);
    cudaGetSymbolAddress((void**)&od,   g_od);
    cudaGetSymbolAddress((void**)&hsA,  g_hsA);
    cudaGetSymbolAddress((void**)&Wcat, g_Wcat);
    cudaGetSymbolAddress((void**)&Wo,   g_Wo);
    cudaGetSymbolAddress((void**)&y,    g_y);

    const int smemG = 3 * (16384 + 16384);   // 98304
    cudaFuncSetAttribute(mma_gemm, cudaFuncAttributeMaxDynamicSharedMemorySize, smemG);

    // 1. hs -> fp16
    cvt_h16_kernel<<<(BT * Dc / 4 + 255) / 256, 256>>>(
        (const float4*)hs, (ushort4*)hsA, BT * Dc / 4);
    // 2. combined W_qkv|W_z transpose into Wcat
    transpose_cat_kernel<<<dim3((CONVD + VALD) / 32, Dc / 32), dim3(32, 8)>>>(
        W_qkv, W_z, Wcat);
    // 3. ab transpose into Wcat rows 8192..8223
    transpose_ab_kernel<<<dim3(Dc / 256, 32), 256>>>(W_a, W_b, Wcat + (size_t)8192 * Dc);
    // 4. fused projections (PROFILED SLOT): mx = hs @ [W_qkv | W_z | W_ab]
    mma_gemm<<<dim3(NCAT / 128, BT / 128), 256, smemG>>>(hsA, Wcat, mx, BT, NCAT, Dc);
    // 5. W_out transpose
    transpose_cvt_kernel<<<dim3(Dc / 32, VALD / 32), dim3(32, 8)>>>(W_out, Wo, VALD, Dc);
    // 6. conv + silu + fused l2norm
    conv_silu_norm_kernel<<<dim3(CONVD / 128, Tc / 256, Bc), 128>>>(mx, conv_w, qkv);
    // 7. a/b activations
    ab_act_kernel<<<(BT * Hc) / 256, 256>>>(mx, dt_bias, A_log, gb);
    // 8. gated delta rule scan
    scan_kernel<<<Bc * Hc * 4, 256>>>(qkv, gb, od);
    // 9. gated RMSNorm -> y fp16
    gate_norm_kernel<<<(BT * Hc) / 8, 256>>>(od, mx, norm_w, (ushort4*)y);
    // 10. out = y @ W_out
    mma_gemm<<<dim3(Dc / 128, BT / 128), 256, smemG>>>(y, Wo, out, BT, Dc, Dc);
}

// round 13
// speedup vs baseline: 2.0286x; 1.0038x over previous
#include <cuda_runtime.h>
#include <cuda_fp16.h>
#include <cstdint>
#include <cstddef>

#define Bc    2
#define Tc    2048
#define Dc    2048
#define Hc    16
#define KEYD  2048
#define VALD  2048
#define CONVD 6144
#define BT    4096   // B*T
#define NCAT  8320   // 6144 qkv | 2048 z | 32 ab | 96 pad

typedef unsigned short u16;
typedef uint32_t u32;

// ---------------- scratch (device globals: allocation-free, zero-init) -------
__device__ float g_mx[(size_t)BT * NCAT];       // fused projection output
__device__ float g_qkv[(size_t)BT * CONVD];     // post conv+silu+l2norm
__device__ float g_od[(size_t)BT * VALD];       // delta-rule output

__device__ u16 g_hsA[(size_t)BT * Dc];
__device__ u16 g_Wcat[(size_t)NCAT * Dc];       // rows 8224.. stay zero
__device__ u16 g_Wo[(size_t)Dc * VALD];
__device__ u16 g_y[(size_t)BT * VALD];

// ---------------- helpers ----------------
__device__ __forceinline__ u16 h16bits(float x) {
    __half h = __float2half_rn(x);
    return *reinterpret_cast<u16*>(&h);
}
__device__ __forceinline__ u32 smem_u32(const void* p) {
    u32 a;
    asm("{ .reg .u64 t; cvta.to.shared.u64 t, %1; cvt.u32.u64 %0, t; }" : "=r"(a) : "l"(p));
    return a;
}
#define SWZ(x) ((x) ^ (((x) >> 3) & 0x70))

__device__ __forceinline__ void cp16(u32 s, const void* g) {
    asm volatile("cp.async.cg.shared.global [%0], [%1], 16;" :: "r"(s), "l"(g));
}
__device__ __forceinline__ void ldsm4(u32* r, u32 a) {
    asm volatile("ldmatrix.sync.aligned.m8n8.x4.shared.b16 {%0,%1,%2,%3}, [%4];"
                 : "=r"(r[0]), "=r"(r[1]), "=r"(r[2]), "=r"(r[3]) : "r"(a));
}
__device__ __forceinline__ void mma16816(float* c, const u32* a, const u32* b) {
    asm volatile(
        "mma.sync.aligned.m16n8k16.row.col.f32.f16.f16.f32 "
        "{%0,%1,%2,%3}, {%4,%5,%6,%7}, {%8,%9}, {%0,%1,%2,%3};"
        : "+f"(c[0]), "+f"(c[1]), "+f"(c[2]), "+f"(c[3])
        : "r"(a[0]), "r"(a[1]), "r"(a[2]), "r"(a[3]), "r"(b[0]), "r"(b[1]));
}

// ---------------- merged prep: cvt(hs) + transpose(Wqkv|Wz) + transpose(ab) --
// blocks [0, 8192)              : hs -> fp16 (2M float4)
// blocks [8192, 8192+16384)     : W_qkv|W_z transpose into Wcat
// blocks [24576, 24576+256)     : Wa/Wb transpose into Wcat rows 8192..8223
#define PREP_CVT_B   8192
#define PREP_CAT_B   16384
#define PREP_AB_B    256
__global__ void prep_all_kernel(const float4* __restrict__ hs4,
                                ushort4* __restrict__ hsA4,
                                const float* __restrict__ Wqkv,
                                const float* __restrict__ Wz,
                                const float* __restrict__ Wa,
                                const float* __restrict__ Wb,
                                u16* __restrict__ Wcat) {
    __shared__ float t[32][33];
    const int blk = blockIdx.x;
    const int tid = threadIdx.y * 32 + threadIdx.x;   // 256
    if (blk < PREP_CVT_B) {
        int i = blk * 256 + tid;          // < 2M
        float4 v = hs4[i];
        ushort4 H;
        H.x = h16bits(v.x); H.y = h16bits(v.y);
        H.z = h16bits(v.z); H.w = h16bits(v.w);
        hsA4[i] = H;
    } else if (blk < PREP_CVT_B + PREP_CAT_B) {
        int b1 = blk - PREP_CVT_B;
        int n0g = (b1 & 255) * 32;
        int k0 = (b1 >> 8) * 32;
        const float* W; int N; int n0;
        if (n0g < CONVD) { W = Wqkv; N = CONVD; n0 = n0g; }
        else             { W = Wz;   N = VALD;  n0 = n0g - CONVD; }
        int x = threadIdx.x, y = threadIdx.y;
#pragma unroll
        for (int i = 0; i < 4; ++i)
            t[y + 8 * i][x] = W[(size_t)(k0 + y + 8 * i) * N + n0 + x];
        __syncthreads();
#pragma unroll
        for (int i = 0; i < 4; ++i)
            Wcat[(size_t)(n0g + y + 8 * i) * Dc + k0 + x] = h16bits(t[x][y + 8 * i]);
    } else {
        int b2 = blk - PREP_CVT_B - PREP_CAT_B;
        int n = b2 >> 3;                  // 0..31
        int k = (b2 & 7) * 256 + tid;     // 0..2047
        const float* W = (n < 16) ? Wa : Wb;
        Wcat[(size_t)(8192 + n) * Dc + k] = h16bits(W[(size_t)k * Hc + (n & 15)]);
    }
}

// W_out transpose
__global__ void transpose_cvt_kernel(const float* __restrict__ W,
                                     u16* __restrict__ Th, int Kd, int N) {
    __shared__ float t[32][33];
    int n0 = blockIdx.x * 32, k0 = blockIdx.y * 32;
    int x = threadIdx.x, y = threadIdx.y;
#pragma unroll
    for (int i = 0; i < 4; ++i)
        t[y + 8 * i][x] = W[(size_t)(k0 + y + 8 * i) * N + n0 + x];
    __syncthreads();
#pragma unroll
    for (int i = 0; i < 4; ++i)
        Th[(size_t)(n0 + y + 8 * i) * Kd + k0 + x] = h16bits(t[x][y + 8 * i]);
}

// ---------------- HMMA GEMM: C[M,N] = A[M,K] @ Bt[N,K]^T ----------------
__global__ __launch_bounds__(256, 2)
void mma_gemm(const u16* __restrict__ A, const u16* __restrict__ Bt,
              float* __restrict__ C, int M, int N, int Kd) {
    extern __shared__ __align__(1024) char smem[];
    constexpr int ATILE = 128 * 128;
    constexpr int STAGE = 2 * ATILE;
    constexpr int MF = 4;
    constexpr int NG = 2;
    const int tid = threadIdx.x, lane = tid & 31, wid = tid >> 5;
    const int wm = (wid & 1) * 64;
    const int wn = (wid >> 1) * 32;
    const int m0 = blockIdx.y * 128, n0 = blockIdx.x * 128;
    const int ktiles = Kd >> 6;
    const u32 sb = smem_u32(smem);

    const u16* Ag = A + (size_t)m0 * Kd;
    const u16* Bg = Bt + (size_t)n0 * Kd;

    auto issue = [&](int kt) {
        const int ko = kt << 6;
        const u32 st = sb + (u32)(kt % 3) * STAGE;
        for (int c = tid; c < 128 * 8; c += 256) {
            int rr = c >> 3, u = c & 7;
            cp16(st + SWZ(rr * 128 + u * 16), Ag + (size_t)rr * Kd + ko + u * 8);
            cp16(st + ATILE + SWZ(rr * 128 + u * 16), Bg + (size_t)rr * Kd + ko + u * 8);
        }
    };

    float acc[MF][4][4];
#pragma unroll
    for (int i = 0; i < MF; ++i)
#pragma unroll
        for (int j = 0; j < 4; ++j)
#pragma unroll
            for (int l = 0; l < 4; ++l) acc[i][j][l] = 0.f;

    issue(0);
    asm volatile("cp.async.commit_group;");
    issue(1);
    asm volatile("cp.async.commit_group;");

    for (int kt = 0; kt < ktiles; ++kt) {
        asm volatile("cp.async.wait_group 1;" ::: "memory");
        __syncthreads();
        if (kt + 2 < ktiles) issue(kt + 2);
        asm volatile("cp.async.commit_group;");

        const u32 Ab = sb + (u32)(kt % 3) * STAGE;
        const u32 Bb = Ab + ATILE;
#pragma unroll
        for (int ks = 0; ks < 4; ++ks) {
            u32 ah[MF][4], bh[NG][4];
            const int arow = wm + (lane & 15);
            const int acol = ks * 32 + ((lane >> 4) << 4);
#pragma unroll
            for (int mf = 0; mf < MF; ++mf)
                ldsm4(ah[mf], Ab + SWZ((arow + mf * 16) * 128 + acol));
            const int brow = wn + (lane & 7) + ((lane >> 4) << 3);
            const int bcol = ks * 32 + ((lane & 8) << 1);
#pragma unroll
            for (int g = 0; g < NG; ++g)
                ldsm4(bh[g], Bb + SWZ((brow + g * 16) * 128 + bcol));
#pragma unroll
            for (int mf = 0; mf < MF; ++mf)
#pragma unroll
                for (int g = 0; g < NG; ++g) {
                    mma16816(acc[mf][2 * g + 0], ah[mf], &bh[g][0]);
                    mma16816(acc[mf][2 * g + 1], ah[mf], &bh[g][2]);
                }
        }
    }

#pragma unroll
    for (int mf = 0; mf < MF; ++mf)
#pragma unroll
        for (int f = 0; f < 4; ++f) {
            int row = m0 + wm + mf * 16 + (lane >> 2);
            int col = n0 + wn + f * 8 + (lane & 3) * 2;
            float2 lo2, hi2;
            lo2.x = acc[mf][f][0]; lo2.y = acc[mf][f][1];
            hi2.x = acc[mf][f][2]; hi2.y = acc[mf][f][3];
            *(float2*)&C[(size_t)row * N + col] = lo2;
            *(float2*)&C[(size_t)(row + 8) * N + col] = hi2;
        }
}

// ---------- depthwise causal conv (K=4) + silu + fused per-head L2 norm ------
__global__ __launch_bounds__(128)
void conv_silu_norm_kernel(const float* __restrict__ mx,
                           const float* __restrict__ cw,
                           float* __restrict__ out) {
    __shared__ float sm[128 * 33];
    __shared__ float ssum[4][32];
    __shared__ float sscale[32];
    const int tid = threadIdx.x;            // 128
    const int xb = blockIdx.x;
    const int c  = xb * 128 + tid;
    const int b  = blockIdx.z;
    const int t0 = blockIdx.y * 256;
    const bool qk = (xb < 32);
    const float qs = (xb < 16) ? 0.08838834764831845f : 1.f;
    const float w0 = cw[c * 4 + 0], w1 = cw[c * 4 + 1];
    const float w2 = cw[c * 4 + 2], w3 = cw[c * 4 + 3];
    const float* base  = mx  + (size_t)b * Tc * NCAT + c;
    float*       obase = out + (size_t)b * Tc * CONVD + c;
    float xm3 = (t0 >= 3) ? base[(size_t)(t0 - 3) * NCAT] : 0.f;
    float xm2 = (t0 >= 2) ? base[(size_t)(t0 - 2) * NCAT] : 0.f;
    float xm1 = (t0 >= 1) ? base[(size_t)(t0 - 1) * NCAT] : 0.f;

    for (int tile = 0; tile < 8; ++tile) {
        const int tb = t0 + tile * 32;
        float yv[32];
#pragma unroll
        for (int u = 0; u < 32; ++u) {
            float x = base[(size_t)(tb + u) * NCAT];
            float y = fmaf(w0, xm3, fmaf(w1, xm2, fmaf(w2, xm1, w3 * x)));
            yv[u] = y / (1.f + expf(-y));
            xm3 = xm2; xm2 = xm1; xm1 = x;
        }
        if (qk) {
#pragma unroll
            for (int u = 0; u < 32; ++u) sm[tid * 33 + u] = yv[u];
            __syncthreads();
            const int tl = tid & 31, grp = tid >> 5;
            float ss = 0.f;
#pragma unroll
            for (int i = 0; i < 32; ++i) {
                float v = sm[(grp * 32 + i) * 33 + tl];
                ss = fmaf(v, v, ss);
            }
            ssum[grp][tl] = ss;
            __syncthreads();
            if (tid < 32)
                sscale[tid] = rsqrtf(ssum[0][tid] + ssum[1][tid] +
                                     ssum[2][tid] + ssum[3][tid] + 1e-6f) * qs;
            __syncthreads();
#pragma unroll
            for (int u = 0; u < 32; ++u)
                obase[(size_t)(tb + u) * CONVD] = yv[u] * sscale[u];
            __syncthreads();
        } else {
#pragma unroll
            for (int u = 0; u < 32; ++u)
                obase[(size_t)(tb + u) * CONVD] = yv[u];
        }
    }
}

// ---------------- gated delta rule scan (+fused a/b activation) -------------
// Prologue: CTA computes g(t), beta(t) for its (b,h) from mx into smem.
__global__ __launch_bounds__(256, 1)
void scan_kernel(const float* __restrict__ qkv, const float* __restrict__ mx,
                 const float* __restrict__ dt_bias, const float* __restrict__ A_log,
                 float* __restrict__ od) {
    __shared__ float sg[Tc];
    __shared__ float sbeta[Tc];
    const int blk  = blockIdx.x;
    const int vblk = blk & 3;
    const int h    = (blk >> 2) & 15;
    const int b    = blk >> 6;
    const int tid = threadIdx.x;
    const int tk = tid & 15, tv = tid >> 4;
    const int vbase = vblk * 32 + tv * 2;

    // fused a/b activation for this (b,h)
    {
        const float dtb = dt_bias[h];
        const float nA = -expf(A_log[h]);
        const float* mxa = mx + (size_t)b * Tc * NCAT + 8192 + h;
        for (int t = tid; t < Tc; t += 256) {
            float av = mxa[(size_t)t * NCAT];
            float bv = mxa[(size_t)t * NCAT + 16];
            float x = av + dtb;
            float sp = (x > 20.f) ? x : log1pf(expf(x));
            sg[t] = nA * sp;
            sbeta[t] = 1.f / (1.f + expf(-bv));
        }
        __syncthreads();
    }

    const float* qp = qkv + (size_t)b * Tc * CONVD + h * 128 + tk * 8;
    const float* kp = qp + KEYD;
    const float* vp = qkv + (size_t)b * Tc * CONVD + 2 * KEYD + h * 128 + vbase;
    float* op = od + ((size_t)b * Tc * Hc + h) * 128 + vbase;

    float S[8][2];
#pragma unroll
    for (int i = 0; i < 8; ++i) { S[i][0] = 0.f; S[i][1] = 0.f; }

    float QA[4][8], KA[4][8], VA[4][2];
    float QB[4][8], KB[4][8], VB[4][2];
    int tg = 0;   // base t of the group currently being computed

#define LOADG(Q, K, V, pred)                                                 \
    {                                                                        \
        if (pred) {                                                          \
            _Pragma("unroll")                                                \
            for (int u = 0; u < 4; ++u) {                                    \
                float4 q0 = *(const float4*)(qp + (size_t)u * CONVD);        \
                float4 q1 = *(const float4*)(qp + (size_t)u * CONVD + 4);    \
                float4 k0 = *(const float4*)(kp + (size_t)u * CONVD);        \
                float4 k1 = *(const float4*)(kp + (size_t)u * CONVD + 4);    \
                float2 vv = *(const float2*)(vp + (size_t)u * CONVD);        \
                Q[u][0] = q0.x; Q[u][1] = q0.y; Q[u][2] = q0.z; Q[u][3] = q0.w; \
                Q[u][4] = q1.x; Q[u][5] = q1.y; Q[u][6] = q1.z; Q[u][7] = q1.w; \
                K[u][0] = k0.x; K[u][1] = k0.y; K[u][2] = k0.z; K[u][3] = k0.w; \
                K[u][4] = k1.x; K[u][5] = k1.y; K[u][6] = k1.z; K[u][7] = k1.w; \
                V[u][0] = vv.x; V[u][1] = vv.y;                              \
            }                                                                \
        }                                                                    \
        qp += 4 * CONVD; kp += 4 * CONVD; vp += 4 * CONVD;                   \
    }

#define COMPG(Q, K, V)                                                       \
    {                                                                        \
        _Pragma("unroll")                                                    \
        for (int u = 0; u < 4; ++u) {                                        \
            float eg = __expf(sg[tg + u]);                                   \
            float bb = sbeta[tg + u];                                        \
            float ks0 = 0.f, ks1 = 0.f, qs0 = 0.f, qs1 = 0.f, qk = 0.f;      \
            _Pragma("unroll")                                                \
            for (int i = 0; i < 8; ++i) {                                    \
                ks0 = fmaf(K[u][i], S[i][0], ks0);                           \
                ks1 = fmaf(K[u][i], S[i][1], ks1);                           \
                qs0 = fmaf(Q[u][i], S[i][0], qs0);                           \
                qs1 = fmaf(Q[u][i], S[i][1], qs1);                           \
                qk  = fmaf(Q[u][i], K[u][i], qk);                            \
            }                                                                \
            _Pragma("unroll")                                                \
            for (int off = 8; off; off >>= 1) {                              \
                ks0 += __shfl_xor_sync(~0u, ks0, off);                       \
                ks1 += __shfl_xor_sync(~0u, ks1, off);                       \
                qs0 += __shfl_xor_sync(~0u, qs0, off);                       \
                qs1 += __shfl_xor_sync(~0u, qs1, off);                       \
                qk  += __shfl_xor_sync(~0u, qk, off);                        \
            }                                                                \
            float d0 = (V[u][0] - eg * ks0) * bb;                            \
            float d1 = (V[u][1] - eg * ks1) * bb;                            \
            if (tk == 0) {                                                   \
                float2 ov;                                                   \
                ov.x = fmaf(qk, d0, eg * qs0);                               \
                ov.y = fmaf(qk, d1, eg * qs1);                               \
                *(float2*)op = ov;                                           \
            }                                                                \
            _Pragma("unroll")                                                \
            for (int i = 0; i < 8; ++i) {                                    \
                S[i][0] = fmaf(K[u][i], d0, eg * S[i][0]);                   \
                S[i][1] = fmaf(K[u][i], d1, eg * S[i][1]);                   \
            }                                                                \
            op += (size_t)Hc * 128;                                          \
        }                                                                    \
        tg += 4;                                                             \
    }

    LOADG(QA, KA, VA, true);
    for (int t = 0; t < Tc; t += 8) {
        LOADG(QB, KB, VB, true);
        COMPG(QA, KA, VA);
        bool pr = (t + 8) < Tc;
        LOADG(QA, KA, VA, pr);
        COMPG(QB, KB, VB);
    }
#undef LOADG
#undef COMPG
}

// ---------------- gated RMSNorm -> fp16 (z from fused buffer) ----------------
__global__ void gate_norm_kernel(const float* __restrict__ od,
                                 const float* __restrict__ mx,
                                 const float* __restrict__ nw,
                                 ushort4* __restrict__ y) {
    const int warp = threadIdx.x >> 5, lane = threadIdx.x & 31;
    const int vec = blockIdx.x * 8 + warp;      // bt*H + h
    const float* opv = od + (size_t)vec * 128 + lane * 4;
    const float* zpv = mx + (size_t)(vec >> 4) * NCAT + 6144 + (vec & 15) * 128 + lane * 4;
    float4 o  = *(const float4*)opv;
    float4 zz = *(const float4*)zpv;
    float4 og;
    og.x = o.x * (zz.x / (1.f + expf(-zz.x)));
    og.y = o.y * (zz.y / (1.f + expf(-zz.y)));
    og.z = o.z * (zz.z / (1.f + expf(-zz.z)));
    og.w = o.w * (zz.w / (1.f + expf(-zz.w)));
    float ss = og.x * og.x + og.y * og.y + og.z * og.z + og.w * og.w;
#pragma unroll
    for (int off = 16; off; off >>= 1) ss += __shfl_xor_sync(~0u, ss, off);
    float r = rsqrtf(ss * (1.f / 128.f) + 1e-6f);
    float4 w = *(const float4*)&nw[lane * 4];
    ushort4 H;
    H.x = h16bits(og.x * r * w.x);
    H.y = h16bits(og.y * r * w.y);
    H.z = h16bits(og.z * r * w.z);
    H.w = h16bits(og.w * r * w.w);
    y[(size_t)vec * 32 + lane] = H;
}

// ---------------- launch ----------------
extern "C" void kernel_launch(void* const* d_in, const int* in_sizes, int n_in,
                              void* d_out, int out_size) {
    const float* hs      = (const float*)d_in[0];
    const float* W_qkv   = (const float*)d_in[1];
    const float* conv_w  = (const float*)d_in[2];
    const float* W_z     = (const float*)d_in[3];
    const float* W_b     = (const float*)d_in[4];
    const float* W_a     = (const float*)d_in[5];
    const float* dt_bias = (const float*)d_in[6];
    const float* A_log   = (const float*)d_in[7];
    const float* norm_w  = (const float*)d_in[8];
    const float* W_out   = (const float*)d_in[9];
    float* out = (float*)d_out;

    float *mx, *qkv, *od;
    u16 *hsA, *Wcat, *Wo, *y;
    cudaGetSymbolAddress((void**)&mx,   g_mx);
    cudaGetSymbolAddress((void**)&qkv,  g_qkv);
    cudaGetSymbolAddress((void**)&od,   g_od);
    cudaGetSymbolAddress((void**)&hsA,  g_hsA);
    cudaGetSymbolAddress((void**)&Wcat, g_Wcat);
    cudaGetSymbolAddress((void**)&Wo,   g_Wo);
    cudaGetSymbolAddress((void**)&y,    g_y);

    const int smemG = 3 * (16384 + 16384);   // 98304
    cudaFuncSetAttribute(mma_gemm, cudaFuncAttributeMaxDynamicSharedMemorySize, smemG);

    // 1. merged prep: hs->fp16 + Wqkv|Wz transpose + ab transpose
    prep_all_kernel<<<PREP_CVT_B + PREP_CAT_B + PREP_AB_B, dim3(32, 8)>>>(
        (const float4*)hs, (ushort4*)hsA, W_qkv, W_z, W_a, W_b, Wcat);
    // 2. fused projections: mx = hs @ [W_qkv | W_z | W_ab]
    mma_gemm<<<dim3(NCAT / 128, BT / 128), 256, smemG>>>(hsA, Wcat, mx, BT, NCAT, Dc);
    // 3. conv + silu + fused l2norm
    conv_silu_norm_kernel<<<dim3(CONVD / 128, Tc / 256, Bc), 128>>>(mx, conv_w, qkv);
    // 4. gated delta rule scan (+ fused a/b activation)  <-- PROFILED SLOT
    scan_kernel<<<Bc * Hc * 4, 256>>>(qkv, mx, dt_bias, A_log, od);
    // 5. W_out transpose
    transpose_cvt_kernel<<<dim3(Dc / 32, VALD / 32), dim3(32, 8)>>>(W_out, Wo, VALD, Dc);
    // 6. gated RMSNorm -> y fp16
    gate_norm_kernel<<<(BT * Hc) / 8, 256>>>(od, mx, norm_w, (ushort4*)y);
    // 7. out = y @ W_out
    mma_gemm<<<dim3(Dc / 128, BT / 128), 256, smemG>>>(y, Wo, out, BT, Dc, Dc);
}

// round 15
// speedup vs baseline: 2.1179x; 1.0440x over previous
#include <cuda_runtime.h>
#include <cuda_fp16.h>
#include <cstdint>
#include <cstddef>

#define Bc    2
#define Tc    2048
#define Dc    2048
#define Hc    16
#define KEYD  2048
#define VALD  2048
#define CONVD 6144
#define BT    4096   // B*T
#define NCAT  8320   // 6144 qkv | 2048 z | 32 ab | 96 pad

typedef unsigned short u16;
typedef uint32_t u32;

// ---------------- scratch (device globals: allocation-free, zero-init) -------
__device__ float g_mx[(size_t)BT * NCAT];       // fused projection output
__device__ float g_qkv[(size_t)BT * CONVD];     // post conv+silu+l2norm
__device__ float g_od[(size_t)BT * VALD];       // delta-rule output

__device__ u16 g_hsA[(size_t)BT * Dc];
__device__ u16 g_Wcat[(size_t)NCAT * Dc];       // rows 8224.. stay zero
__device__ u16 g_Wo[(size_t)Dc * VALD];
__device__ u16 g_y[(size_t)BT * VALD];

// ---------------- helpers ----------------
__device__ __forceinline__ u16 h16bits(float x) {
    __half h = __float2half_rn(x);
    return *reinterpret_cast<u16*>(&h);
}
__device__ __forceinline__ u32 smem_u32(const void* p) {
    u32 a;
    asm("{ .reg .u64 t; cvta.to.shared.u64 t, %1; cvt.u32.u64 %0, t; }" : "=r"(a) : "l"(p));
    return a;
}
#define SWZ(x) ((x) ^ (((x) >> 3) & 0x70))

__device__ __forceinline__ void cp16(u32 s, const void* g) {
    asm volatile("cp.async.cg.shared.global [%0], [%1], 16;" :: "r"(s), "l"(g));
}
__device__ __forceinline__ void ldsm4(u32* r, u32 a) {
    asm volatile("ldmatrix.sync.aligned.m8n8.x4.shared.b16 {%0,%1,%2,%3}, [%4];"
                 : "=r"(r[0]), "=r"(r[1]), "=r"(r[2]), "=r"(r[3]) : "r"(a));
}
__device__ __forceinline__ void mma16816(float* c, const u32* a, const u32* b) {
    asm volatile(
        "mma.sync.aligned.m16n8k16.row.col.f32.f16.f16.f32 "
        "{%0,%1,%2,%3}, {%4,%5,%6,%7}, {%8,%9}, {%0,%1,%2,%3};"
        : "+f"(c[0]), "+f"(c[1]), "+f"(c[2]), "+f"(c[3])
        : "r"(a[0]), "r"(a[1]), "r"(a[2]), "r"(a[3]), "r"(b[0]), "r"(b[1]));
}

// ---------------- merged prep: cvt(hs) + transpose(Wqkv|Wz) + transpose(ab) --
#define PREP_CVT_B   8192
#define PREP_CAT_B   16384
#define PREP_AB_B    256
__global__ void prep_all_kernel(const float4* __restrict__ hs4,
                                ushort4* __restrict__ hsA4,
                                const float* __restrict__ Wqkv,
                                const float* __restrict__ Wz,
                                const float* __restrict__ Wa,
                                const float* __restrict__ Wb,
                                u16* __restrict__ Wcat) {
    __shared__ float t[32][33];
    const int blk = blockIdx.x;
    const int tid = threadIdx.y * 32 + threadIdx.x;   // 256
    if (blk < PREP_CVT_B) {
        int i = blk * 256 + tid;
        float4 v = hs4[i];
        ushort4 H;
        H.x = h16bits(v.x); H.y = h16bits(v.y);
        H.z = h16bits(v.z); H.w = h16bits(v.w);
        hsA4[i] = H;
    } else if (blk < PREP_CVT_B + PREP_CAT_B) {
        int b1 = blk - PREP_CVT_B;
        int n0g = (b1 & 255) * 32;
        int k0 = (b1 >> 8) * 32;
        const float* W; int N; int n0;
        if (n0g < CONVD) { W = Wqkv; N = CONVD; n0 = n0g; }
        else             { W = Wz;   N = VALD;  n0 = n0g - CONVD; }
        int x = threadIdx.x, y = threadIdx.y;
#pragma unroll
        for (int i = 0; i < 4; ++i)
            t[y + 8 * i][x] = W[(size_t)(k0 + y + 8 * i) * N + n0 + x];
        __syncthreads();
#pragma unroll
        for (int i = 0; i < 4; ++i)
            Wcat[(size_t)(n0g + y + 8 * i) * Dc + k0 + x] = h16bits(t[x][y + 8 * i]);
    } else {
        int b2 = blk - PREP_CVT_B - PREP_CAT_B;
        int n = b2 >> 3;
        int k = (b2 & 7) * 256 + tid;
        const float* W = (n < 16) ? Wa : Wb;
        Wcat[(size_t)(8192 + n) * Dc + k] = h16bits(W[(size_t)k * Hc + (n & 15)]);
    }
}

// W_out transpose
__global__ void transpose_cvt_kernel(const float* __restrict__ W,
                                     u16* __restrict__ Th, int Kd, int N) {
    __shared__ float t[32][33];
    int n0 = blockIdx.x * 32, k0 = blockIdx.y * 32;
    int x = threadIdx.x, y = threadIdx.y;
#pragma unroll
    for (int i = 0; i < 4; ++i)
        t[y + 8 * i][x] = W[(size_t)(k0 + y + 8 * i) * N + n0 + x];
    __syncthreads();
#pragma unroll
    for (int i = 0; i < 4; ++i)
        Th[(size_t)(n0 + y + 8 * i) * Kd + k0 + x] = h16bits(t[x][y + 8 * i]);
}

// ---------------- HMMA GEMM: C[M,N] = A[M,K] @ Bt[N,K]^T ----------------
__global__ __launch_bounds__(256, 2)
void mma_gemm(const u16* __restrict__ A, const u16* __restrict__ Bt,
              float* __restrict__ C, int M, int N, int Kd) {
    extern __shared__ __align__(1024) char smem[];
    constexpr int ATILE = 128 * 128;
    constexpr int STAGE = 2 * ATILE;
    constexpr int MF = 4;
    constexpr int NG = 2;
    const int tid = threadIdx.x, lane = tid & 31, wid = tid >> 5;
    const int wm = (wid & 1) * 64;
    const int wn = (wid >> 1) * 32;
    const int m0 = blockIdx.y * 128, n0 = blockIdx.x * 128;
    const int ktiles = Kd >> 6;
    const u32 sb = smem_u32(smem);

    const u16* Ag = A + (size_t)m0 * Kd;
    const u16* Bg = Bt + (size_t)n0 * Kd;

    auto issue = [&](int kt) {
        const int ko = kt << 6;
        const u32 st = sb + (u32)(kt % 3) * STAGE;
        for (int c = tid; c < 128 * 8; c += 256) {
            int rr = c >> 3, u = c & 7;
            cp16(st + SWZ(rr * 128 + u * 16), Ag + (size_t)rr * Kd + ko + u * 8);
            cp16(st + ATILE + SWZ(rr * 128 + u * 16), Bg + (size_t)rr * Kd + ko + u * 8);
        }
    };

    float acc[MF][4][4];
#pragma unroll
    for (int i = 0; i < MF; ++i)
#pragma unroll
        for (int j = 0; j < 4; ++j)
#pragma unroll
            for (int l = 0; l < 4; ++l) acc[i][j][l] = 0.f;

    issue(0);
    asm volatile("cp.async.commit_group;");
    issue(1);
    asm volatile("cp.async.commit_group;");

    for (int kt = 0; kt < ktiles; ++kt) {
        asm volatile("cp.async.wait_group 1;" ::: "memory");
        __syncthreads();
        if (kt + 2 < ktiles) issue(kt + 2);
        asm volatile("cp.async.commit_group;");

        const u32 Ab = sb + (u32)(kt % 3) * STAGE;
        const u32 Bb = Ab + ATILE;
#pragma unroll
        for (int ks = 0; ks < 4; ++ks) {
            u32 ah[MF][4], bh[NG][4];
            const int arow = wm + (lane & 15);
            const int acol = ks * 32 + ((lane >> 4) << 4);
#pragma unroll
            for (int mf = 0; mf < MF; ++mf)
                ldsm4(ah[mf], Ab + SWZ((arow + mf * 16) * 128 + acol));
            const int brow = wn + (lane & 7) + ((lane >> 4) << 3);
            const int bcol = ks * 32 + ((lane & 8) << 1);
#pragma unroll
            for (int g = 0; g < NG; ++g)
                ldsm4(bh[g], Bb + SWZ((brow + g * 16) * 128 + bcol));
#pragma unroll
            for (int mf = 0; mf < MF; ++mf)
#pragma unroll
                for (int g = 0; g < NG; ++g) {
                    mma16816(acc[mf][2 * g + 0], ah[mf], &bh[g][0]);
                    mma16816(acc[mf][2 * g + 1], ah[mf], &bh[g][2]);
                }
        }
    }

#pragma unroll
    for (int mf = 0; mf < MF; ++mf)
#pragma unroll
        for (int f = 0; f < 4; ++f) {
            int row = m0 + wm + mf * 16 + (lane >> 2);
            int col = n0 + wn + f * 8 + (lane & 3) * 2;
            float2 lo2, hi2;
            lo2.x = acc[mf][f][0]; lo2.y = acc[mf][f][1];
            hi2.x = acc[mf][f][2]; hi2.y = acc[mf][f][3];
            *(float2*)&C[(size_t)row * N + col] = lo2;
            *(float2*)&C[(size_t)(row + 8) * N + col] = hi2;
        }
}

// ---------- depthwise causal conv (K=4) + silu + fused per-head L2 norm ------
__global__ __launch_bounds__(128)
void conv_silu_norm_kernel(const float* __restrict__ mx,
                           const float* __restrict__ cw,
                           float* __restrict__ out) {
    __shared__ float sm[128 * 33];
    __shared__ float ssum[4][32];
    __shared__ float sscale[32];
    const int tid = threadIdx.x;
    const int xb = blockIdx.x;
    const int c  = xb * 128 + tid;
    const int b  = blockIdx.z;
    const int t0 = blockIdx.y * 256;
    const bool qk = (xb < 32);
    const float qs = (xb < 16) ? 0.08838834764831845f : 1.f;
    const float w0 = cw[c * 4 + 0], w1 = cw[c * 4 + 1];
    const float w2 = cw[c * 4 + 2], w3 = cw[c * 4 + 3];
    const float* base  = mx  + (size_t)b * Tc * NCAT + c;
    float*       obase = out + (size_t)b * Tc * CONVD + c;
    float xm3 = (t0 >= 3) ? base[(size_t)(t0 - 3) * NCAT] : 0.f;
    float xm2 = (t0 >= 2) ? base[(size_t)(t0 - 2) * NCAT] : 0.f;
    float xm1 = (t0 >= 1) ? base[(size_t)(t0 - 1) * NCAT] : 0.f;

    for (int tile = 0; tile < 8; ++tile) {
        const int tb = t0 + tile * 32;
        float yv[32];
#pragma unroll
        for (int u = 0; u < 32; ++u) {
            float x = base[(size_t)(tb + u) * NCAT];
            float y = fmaf(w0, xm3, fmaf(w1, xm2, fmaf(w2, xm1, w3 * x)));
            yv[u] = y / (1.f + expf(-y));
            xm3 = xm2; xm2 = xm1; xm1 = x;
        }
        if (qk) {
#pragma unroll
            for (int u = 0; u < 32; ++u) sm[tid * 33 + u] = yv[u];
            __syncthreads();
            const int tl = tid & 31, grp = tid >> 5;
            float ss = 0.f;
#pragma unroll
            for (int i = 0; i < 32; ++i) {
                float v = sm[(grp * 32 + i) * 33 + tl];
                ss = fmaf(v, v, ss);
            }
            ssum[grp][tl] = ss;
            __syncthreads();
            if (tid < 32)
                sscale[tid] = rsqrtf(ssum[0][tid] + ssum[1][tid] +
                                     ssum[2][tid] + ssum[3][tid] + 1e-6f) * qs;
            __syncthreads();
#pragma unroll
            for (int u = 0; u < 32; ++u)
                obase[(size_t)(tb + u) * CONVD] = yv[u] * sscale[u];
            __syncthreads();
        } else {
#pragma unroll
            for (int u = 0; u < 32; ++u)
                obase[(size_t)(tb + u) * CONVD] = yv[u];
        }
    }
}

// ---------------- gated delta rule scan (+fused a/b activation) -------------
// o_t = q_t . S_t (post-update) -- removes the qk reduction entirely.
// Output reductions are batched over groups of 4 timesteps (off critical path).
__global__ __launch_bounds__(256, 1)
void scan_kernel(const float* __restrict__ qkv, const float* __restrict__ mx,
                 const float* __restrict__ dt_bias, const float* __restrict__ A_log,
                 float* __restrict__ od) {
    __shared__ float sg[Tc];
    __shared__ float sbeta[Tc];
    const int blk  = blockIdx.x;
    const int vblk = blk & 3;
    const int h    = (blk >> 2) & 15;
    const int b    = blk >> 6;
    const int tid = threadIdx.x;
    const int tk = tid & 15, tv = tid >> 4;
    const int vbase = vblk * 32 + tv * 2;

    // fused a/b activation for this (b,h)
    {
        const float dtb = dt_bias[h];
        const float nA = -expf(A_log[h]);
        const float* mxa = mx + (size_t)b * Tc * NCAT + 8192 + h;
        for (int t = tid; t < Tc; t += 256) {
            float av = mxa[(size_t)t * NCAT];
            float bv = mxa[(size_t)t * NCAT + 16];
            float x = av + dtb;
            float sp = (x > 20.f) ? x : log1pf(expf(x));
            sg[t] = nA * sp;
            sbeta[t] = 1.f / (1.f + expf(-bv));
        }
        __syncthreads();
    }

    const float* qp = qkv + (size_t)b * Tc * CONVD + h * 128 + tk * 8;
    const float* kp = qp + KEYD;
    const float* vp = qkv + (size_t)b * Tc * CONVD + 2 * KEYD + h * 128 + vbase;
    float* op = od + ((size_t)b * Tc * Hc + h) * 128 + vbase;

    float S[8][2];
#pragma unroll
    for (int i = 0; i < 8; ++i) { S[i][0] = 0.f; S[i][1] = 0.f; }

    float QA[4][8], KA[4][8], VA[4][2];
    float QB[4][8], KB[4][8], VB[4][2];
    int tg = 0;

#define LOADG(Q, K, V, pred)                                                 \
    {                                                                        \
        if (pred) {                                                          \
            _Pragma("unroll")                                                \
            for (int u = 0; u < 4; ++u) {                                    \
                float4 q0 = *(const float4*)(qp + (size_t)u * CONVD);        \
                float4 q1 = *(const float4*)(qp + (size_t)u * CONVD + 4);    \
                float4 k0 = *(const float4*)(kp + (size_t)u * CONVD);        \
                float4 k1 = *(const float4*)(kp + (size_t)u * CONVD + 4);    \
                float2 vv = *(const float2*)(vp + (size_t)u * CONVD);        \
                Q[u][0] = q0.x; Q[u][1] = q0.y; Q[u][2] = q0.z; Q[u][3] = q0.w; \
                Q[u][4] = q1.x; Q[u][5] = q1.y; Q[u][6] = q1.z; Q[u][7] = q1.w; \
                K[u][0] = k0.x; K[u][1] = k0.y; K[u][2] = k0.z; K[u][3] = k0.w; \
                K[u][4] = k1.x; K[u][5] = k1.y; K[u][6] = k1.z; K[u][7] = k1.w; \
                V[u][0] = vv.x; V[u][1] = vv.y;                              \
            }                                                                \
        }                                                                    \
        qp += 4 * CONVD; kp += 4 * CONVD; vp += 4 * CONVD;                   \
    }

#define COMPG(Q, K, V)                                                       \
    {                                                                        \
        float eg4[4], bb4[4];                                                \
        _Pragma("unroll")                                                    \
        for (int u = 0; u < 4; ++u) {                                        \
            eg4[u] = __expf(sg[tg + u]);                                     \
            bb4[u] = sbeta[tg + u];                                          \
        }                                                                    \
        float OS0[4], OS1[4];                                                \
        _Pragma("unroll")                                                    \
        for (int u = 0; u < 4; ++u) {                                        \
            const float eg = eg4[u], bb = bb4[u];                            \
            float ks0 = 0.f, ks1 = 0.f;                                      \
            _Pragma("unroll")                                                \
            for (int i = 0; i < 8; ++i) {                                    \
                ks0 = fmaf(K[u][i], S[i][0], ks0);                           \
                ks1 = fmaf(K[u][i], S[i][1], ks1);                           \
            }                                                                \
            _Pragma("unroll")                                                \
            for (int off = 8; off; off >>= 1) {                              \
                ks0 += __shfl_xor_sync(~0u, ks0, off);                       \
                ks1 += __shfl_xor_sync(~0u, ks1, off);                       \
            }                                                                \
            float d0 = (V[u][0] - eg * ks0) * bb;                            \
            float d1 = (V[u][1] - eg * ks1) * bb;                            \
            float os0 = 0.f, os1 = 0.f;                                      \
            _Pragma("unroll")                                                \
            for (int i = 0; i < 8; ++i) {                                    \
                S[i][0] = fmaf(K[u][i], d0, eg * S[i][0]);                   \
                os0 = fmaf(Q[u][i], S[i][0], os0);                           \
                S[i][1] = fmaf(K[u][i], d1, eg * S[i][1]);                   \
                os1 = fmaf(Q[u][i], S[i][1], os1);                           \
            }                                                                \
            OS0[u] = os0; OS1[u] = os1;                                      \
        }                                                                    \
        _Pragma("unroll")                                                    \
        for (int off = 8; off; off >>= 1) {                                  \
            _Pragma("unroll")                                                \
            for (int u = 0; u < 4; ++u) {                                    \
                OS0[u] += __shfl_xor_sync(~0u, OS0[u], off);                 \
                OS1[u] += __shfl_xor_sync(~0u, OS1[u], off);                 \
            }                                                                \
        }                                                                    \
        if (tk == 0) {                                                       \
            _Pragma("unroll")                                                \
            for (int u = 0; u < 4; ++u) {                                    \
                float2 ov; ov.x = OS0[u]; ov.y = OS1[u];                     \
                *(float2*)(op + (size_t)u * Hc * 128) = ov;                  \
            }                                                                \
        }                                                                    \
        op += (size_t)4 * Hc * 128;                                          \
        tg += 4;                                                             \
    }

    LOADG(QA, KA, VA, true);
    for (int t = 0; t < Tc; t += 8) {
        LOADG(QB, KB, VB, true);
        COMPG(QA, KA, VA);
        bool pr = (t + 8) < Tc;
        LOADG(QA, KA, VA, pr);
        COMPG(QB, KB, VB);
    }
#undef LOADG
#undef COMPG
}

// ---------------- gated RMSNorm -> fp16 (z from fused buffer) ----------------
__global__ void gate_norm_kernel(const float* __restrict__ od,
                                 const float* __restrict__ mx,
                                 const float* __restrict__ nw,
                                 ushort4* __restrict__ y) {
    const int warp = threadIdx.x >> 5, lane = threadIdx.x & 31;
    const int vec = blockIdx.x * 8 + warp;
    const float* opv = od + (size_t)vec * 128 + lane * 4;
    const float* zpv = mx + (size_t)(vec >> 4) * NCAT + 6144 + (vec & 15) * 128 + lane * 4;
    float4 o  = *(const float4*)opv;
    float4 zz = *(const float4*)zpv;
    float4 og;
    og.x = o.x * (zz.x / (1.f + expf(-zz.x)));
    og.y = o.y * (zz.y / (1.f + expf(-zz.y)));
    og.z = o.z * (zz.z / (1.f + expf(-zz.z)));
    og.w = o.w * (zz.w / (1.f + expf(-zz.w)));
    float ss = og.x * og.x + og.y * og.y + og.z * og.z + og.w * og.w;
#pragma unroll
    for (int off = 16; off; off >>= 1) ss += __shfl_xor_sync(~0u, ss, off);
    float r = rsqrtf(ss * (1.f / 128.f) + 1e-6f);
    float4 w = *(const float4*)&nw[lane * 4];
    ushort4 H;
    H.x = h16bits(og.x * r * w.x);
    H.y = h16bits(og.y * r * w.y);
    H.z = h16bits(og.z * r * w.z);
    H.w = h16bits(og.w * r * w.w);
    y[(size_t)vec * 32 + lane] = H;
}

// ---------------- launch ----------------
extern "C" void kernel_launch(void* const* d_in, const int* in_sizes, int n_in,
                              void* d_out, int out_size) {
    const float* hs      = (const float*)d_in[0];
    const float* W_qkv   = (const float*)d_in[1];
    const float* conv_w  = (const float*)d_in[2];
    const float* W_z     = (const float*)d_in[3];
    const float* W_b     = (const float*)d_in[4];
    const float* W_a     = (const float*)d_in[5];
    const float* dt_bias = (const float*)d_in[6];
    const float* A_log   = (const float*)d_in[7];
    const float* norm_w  = (const float*)d_in[8];
    const float* W_out   = (const float*)d_in[9];
    float* out = (float*)d_out;

    float *mx, *qkv, *od;
    u16 *hsA, *Wcat, *Wo, *y;
    cudaGetSymbolAddress((void**)&mx,   g_mx);
    cudaGetSymbolAddress((void**)&qkv,  g_qkv);
    cudaGetSymbolAddress((void**)&od,   g_od);
    cudaGetSymbolAddress((void**)&hsA,  g_hsA);
    cudaGetSymbolAddress((void**)&Wcat, g_Wcat);
    cudaGetSymbolAddress((void**)&Wo,   g_Wo);
    cudaGetSymbolAddress((void**)&y,    g_y);

    const int smemG = 3 * (16384 + 16384);   // 98304
    cudaFuncSetAttribute(mma_gemm, cudaFuncAttributeMaxDynamicSharedMemorySize, smemG);

    // 1. merged prep
    prep_all_kernel<<<PREP_CVT_B + PREP_CAT_B + PREP_AB_B, dim3(32, 8)>>>(
        (const float4*)hs, (ushort4*)hsA, W_qkv, W_z, W_a, W_b, Wcat);
    // 2. fused projections
    mma_gemm<<<dim3(NCAT / 128, BT / 128), 256, smemG>>>(hsA, Wcat, mx, BT, NCAT, Dc);
    // 3. conv + silu + fused l2norm
    conv_silu_norm_kernel<<<dim3(CONVD / 128, Tc / 256, Bc), 128>>>(mx, conv_w, qkv);
    // 4. gated delta rule scan  <-- PROFILED SLOT
    scan_kernel<<<Bc * Hc * 4, 256>>>(qkv, mx, dt_bias, A_log, od);
    // 5. W_out transpose
    transpose_cvt_kernel<<<dim3(Dc / 32, VALD / 32), dim3(32, 8)>>>(W_out, Wo, VALD, Dc);
    // 6. gated RMSNorm -> y fp16
    gate_norm_kernel<<<(BT * Hc) / 8, 256>>>(od, mx, norm_w, (ushort4*)y);
    // 7. out = y @ W_out
    mma_gemm<<<dim3(Dc / 128, BT / 128), 256, smemG>>>(y, Wo, out, BT, Dc, Dc);
}